// round 10
// baseline (speedup 1.0000x reference)
#include <cuda_runtime.h>
#include <cuda_bf16.h>
#include <cstdint>
#include <cstddef>

// ---------------------------------------------------------------------------
// Constants (total_steps=1000 -> K=10 bins of S=100)
// ---------------------------------------------------------------------------
#define T_STEPS 1000
#define SBIN    100
#define KBINS   10

#define H0 100
#define W0 368
#define H1 50
#define W1 184
#define H2 25
#define W2 92
#define H3 13
#define W3 46
#define H4 7
#define W4 23

#define P0 (H0*W0)   // 36800
#define P1 (H1*W1)   // 9200
#define P2 (H2*W2)   // 2300
#define P3 (H3*W3)   // 598
#define P4 (H4*W4)   // 161

#define N1 (4*P1)    // 36800
#define N2 (8*P2)    // 18400
#define N3 (16*P3)   // 9568
#define N4 (32*P4)   // 5152

// ---------------------------------------------------------------------------
// Scratch (device globals; allocation-free per harness rules).
// g_c1 is GONE: layer 1 conv+scan are fused (no materialized currents).
// ---------------------------------------------------------------------------
__device__ unsigned char g_s1[(size_t)T_STEPS * N1];
__device__ float         g_c2[(size_t)T_STEPS * N2];
__device__ unsigned char g_s2[(size_t)T_STEPS * N2];
__device__ float         g_c3[(size_t)T_STEPS * N3];
__device__ unsigned char g_s3[(size_t)T_STEPS * N3];
__device__ float         g_c4[(size_t)T_STEPS * N4];

__device__ float g_skip1[80  * P1];
__device__ float g_skip2[160 * P2];
__device__ float g_skip3[320 * P3];
__device__ float g_skip4[640 * P4];

__device__ float g_d4[64 * P4];
__device__ float g_u4[64 * P3];
__device__ float g_d3[32 * P3];
__device__ float g_u3[32 * P2];
__device__ float g_d2[16 * P2];
__device__ float g_u2[16 * P1];
__device__ float g_d1[8  * P1];
__device__ float g_u1[8  * P0];

// Device-side buffer selectors (compile-time)
template<int L> __device__ __forceinline__ float* cbuf_of() {
    if constexpr (L == 2) return g_c2;
    else if constexpr (L == 3) return g_c3;
    else return g_c4;
}
template<int L> __device__ __forceinline__ unsigned char* sbuf_of() {
    if constexpr (L == 1) return g_s1;
    else if constexpr (L == 2) return g_s2;
    else return g_s3;
}
template<int L> __device__ __forceinline__ float* skip_of() {
    if constexpr (L == 1) return g_skip1;
    else if constexpr (L == 2) return g_skip2;
    else if constexpr (L == 3) return g_skip3;
    else return g_skip4;
}

// ---------------------------------------------------------------------------
// FUSED layer 1: conv(stride2) + membrane scan, one thread per neuron (c,pos).
// Eliminates the 147MB g_c1 write + 147MB re-read. The 3x3 window of x is
// double-buffered in named registers (A/B) so t+1's loads overlap t's
// FMA+membrane chain. Tap order and scan arithmetic are bitwise identical to
// the previous split kernels (invalid taps contribute exact +0.0f).
// ---------------------------------------------------------------------------
__device__ __forceinline__ void l1_loadx(const float* __restrict__ x, int t,
                                         int off, bool rv2, bool cv2,
                                         float (&d)[9]) {
    const float* xt = x + (size_t)t * P0 + off;
    d[0] = __ldg(xt);
    d[1] = __ldg(xt + 1);
    d[2] = cv2 ? __ldg(xt + 2) : 0.0f;
    d[3] = __ldg(xt + W0);
    d[4] = __ldg(xt + W0 + 1);
    d[5] = cv2 ? __ldg(xt + W0 + 2) : 0.0f;
    d[6] = rv2 ? __ldg(xt + 2 * W0) : 0.0f;
    d[7] = rv2 ? __ldg(xt + 2 * W0 + 1) : 0.0f;
    d[8] = (rv2 && cv2) ? __ldg(xt + 2 * W0 + 2) : 0.0f;
}

__device__ __forceinline__ void l1_step(const float (&xv)[9], const float (&w)[9],
                                        float bias, int t, int n,
                                        float& m, float& sum, float& sq) {
    float cur = bias;
    #pragma unroll
    for (int j = 0; j < 9; j++) cur = __fmaf_rn(xv[j], w[j], cur);
    // exact mul-then-add mirrors BETA*m + conv
    m = __fadd_rn(__fmul_rn(0.9f, m), cur);
    bool spk = (m > 1.0f);                  // == (m - 1 > 0) exactly in fp32
    g_s1[(size_t)t * N1 + n] = spk ? (unsigned char)1 : (unsigned char)0;
    if (spk) m = __fadd_rn(m, -1.0f);       // soft reset (exact, Sterbenz)
    sum = __fadd_rn(sum, m);
    sq  = __fmaf_rn(m, m, sq);
}

__global__ void fused_l1_kernel(const float* __restrict__ x,
                                const float* __restrict__ w1,
                                const float* __restrict__ b1) {
    int n = blockIdx.x * blockDim.x + threadIdx.x;
    if (n >= N1) return;
    int c = n / P1, pos = n - c * P1;
    int oh = pos / W1, ow = pos - oh * W1;

    float w[9];
    #pragma unroll
    for (int j = 0; j < 9; j++) w[j] = __ldg(&w1[c * 9 + j]);
    float bias = __ldg(&b1[c]);

    const int r0 = 2 * oh, c0 = 2 * ow;
    const int off = r0 * W0 + c0;
    const bool rv2 = (r0 + 2 < H0);     // rows r0, r0+1 always valid
    const bool cv2 = (c0 + 2 < W0);     // cols c0, c0+1 always valid

    float A[9], B[9];
    l1_loadx(x, 0, off, rv2, cv2, A);

    float m = 0.0f;
    int t = 0;
    for (int k = 0; k < KBINS; k++) {
        float sum = 0.0f, sq = 0.0f;
        #pragma unroll 1
        for (int s2 = 0; s2 < SBIN / 2; s2++) {
            if (t + 1 < T_STEPS) l1_loadx(x, t + 1, off, rv2, cv2, B);
            l1_step(A, w, bias, t, n, m, sum, sq);
            t++;
            if (t + 1 < T_STEPS) l1_loadx(x, t + 1, off, rv2, cv2, A);
            l1_step(B, w, bias, t, n, m, sum, sq);
            t++;
        }
        float mu  = __fdiv_rn(sum, (float)SBIN);
        float var = __fsub_rn(__fdiv_rn(sq, (float)SBIN), __fmul_rn(mu, mu));
        float sd  = __fsqrt_rn(fmaxf(var, 1e-8f));
        g_skip1[(size_t)(k * 8 + c) * P1 + pos]     = mu;
        g_skip1[(size_t)(k * 8 + 4 + c) * P1 + pos] = sd;
    }
}

// ---------------------------------------------------------------------------
// Spike conv (stride 2, SAME): spikes of layer L-1 -> currents of layer L.
// ---------------------------------------------------------------------------
template<int L, int CIN, int COUT, int IH, int IW, int OH, int OW, int PH>
__global__ void convs_kernel(const float* __restrict__ w,
                             const float* __restrict__ b) {
    constexpr int P  = OH * OW;
    constexpr int NI = CIN * IH * IW;
    constexpr int NW = CIN * 9 * COUT;
    const unsigned char* __restrict__ spk = sbuf_of<L - 1>();
    float* __restrict__ cbuf = cbuf_of<L>();

    __shared__ __align__(16) float ws[NW];
    __shared__ float bs[COUT];
    for (int i = threadIdx.x; i < NW; i += blockDim.x) {
        int oc = i / (CIN * 9);
        int j  = i - oc * (CIN * 9);        // ic*9 + tap
        ws[j * COUT + oc] = w[i];
    }
    for (int i = threadIdx.x; i < COUT; i += blockDim.x) bs[i] = b[i];
    __syncthreads();

    int idx = blockIdx.x * blockDim.x + threadIdx.x;
    if (idx >= T_STEPS * P) return;
    int t = idx / P;
    int pos = idx - t * P;
    int oh = pos / OW, ow = pos - oh * OW;

    float acc[COUT];
    #pragma unroll
    for (int o = 0; o < COUT; o++) acc[o] = bs[o];

    const unsigned char* sp = spk + (size_t)t * NI;
    #pragma unroll
    for (int kh = 0; kh < 3; kh++) {
        int r = 2 * oh + kh - PH;
        if (r < 0 || r >= IH) continue;
        #pragma unroll
        for (int kw = 0; kw < 3; kw++) {
            int cc = 2 * ow + kw;
            if (cc >= IW) continue;
            int tap = kh * 3 + kw;
            #pragma unroll
            for (int ic = 0; ic < CIN; ic++) {
                if (sp[ic * (IH * IW) + r * IW + cc]) {
                    const float* wv = &ws[(ic * 9 + tap) * COUT];
                    #pragma unroll
                    for (int o = 0; o < COUT; o++)
                        acc[o] = __fadd_rn(acc[o], wv[o]);
                }
            }
        }
    }
    float* out = cbuf + (size_t)t * (COUT * P) + pos;
    #pragma unroll
    for (int o = 0; o < COUT; o++) out[o * P] = acc[o];
}

// ---------------------------------------------------------------------------
// Per-neuron membrane scan (layers 2-4), spill-free: UF=25, A/B named buffers
// with COMPILE-TIME selection; 4 groups per 100-step bin.
// ---------------------------------------------------------------------------
template<int N, bool WRITE_S>
__device__ __forceinline__ void scan_group(const float* __restrict__ cp,
                                           unsigned char* __restrict__ sb,
                                           int tproc,
                                           float (&proc)[25], float (&pre)[25],
                                           float& m, float& sum, float& sq) {
    const int tpre = tproc + 25;
    const bool dopre = (tpre < T_STEPS);
    if (dopre) {
        #pragma unroll
        for (int j = 0; j < 25; j++)
            pre[j] = __ldg(cp + (size_t)(tpre + j) * N);
    }
    #pragma unroll
    for (int j = 0; j < 25; j++) {
        m = __fadd_rn(__fmul_rn(0.9f, m), proc[j]);
        bool spk = (m > 1.0f);
        if (WRITE_S)
            sb[(size_t)(tproc + j) * N] = spk ? (unsigned char)1
                                              : (unsigned char)0;
        if (spk) m = __fadd_rn(m, -1.0f);
        sum = __fadd_rn(sum, m);
        sq  = __fmaf_rn(m, m, sq);
    }
}

template<int L, int C, int P, bool WRITE_S>
__global__ void scan_kernel() {
    constexpr int N = C * P;
    const float* __restrict__ cbuf = cbuf_of<L>();
    float* __restrict__ skip = skip_of<L>();

    int n = blockIdx.x * blockDim.x + threadIdx.x;
    if (n >= N) return;
    int c = n / P, pos = n - c * P;

    const float* cp = cbuf + n;
    unsigned char* sb = WRITE_S ? (sbuf_of<L>() + n) : (unsigned char*)0;

    float A[25], B[25];
    #pragma unroll
    for (int j = 0; j < 25; j++) A[j] = __ldg(cp + (size_t)j * N);

    float m = 0.0f;
    int t = 0;
    for (int k = 0; k < KBINS; k++) {
        float sum = 0.0f, sq = 0.0f;
        scan_group<N, WRITE_S>(cp, sb, t, A, B, m, sum, sq); t += 25;
        scan_group<N, WRITE_S>(cp, sb, t, B, A, m, sum, sq); t += 25;
        scan_group<N, WRITE_S>(cp, sb, t, A, B, m, sum, sq); t += 25;
        scan_group<N, WRITE_S>(cp, sb, t, B, A, m, sum, sq); t += 25;

        float mu  = __fdiv_rn(sum, (float)SBIN);
        float var = __fsub_rn(__fdiv_rn(sq, (float)SBIN), __fmul_rn(mu, mu));
        float sd  = __fsqrt_rn(fmaxf(var, 1e-8f));
        skip[(size_t)(k * 2 * C + c) * P + pos]     = mu;
        skip[(size_t)(k * 2 * C + C + c) * P + pos] = sd;
    }
}

// ---------------------------------------------------------------------------
// Decoder conv: stride 1, SAME (pad 1), input = concat(in1[C1], in2[C2]).
// ---------------------------------------------------------------------------
template<int STAGE, int C1, int C2, int COUT, int HH, int WW>
__global__ void dconv_kernel(const float* __restrict__ w,
                             const float* __restrict__ b) {
    constexpr int P = HH * WW;
    constexpr int CTOT = C1 + C2;
    const float* in1;
    const float* in2;
    float* outp;
    if constexpr (STAGE == 4) { in1 = g_skip4; in2 = nullptr; outp = g_d4; }
    else if constexpr (STAGE == 3) { in1 = g_u4; in2 = g_skip3; outp = g_d3; }
    else if constexpr (STAGE == 2) { in1 = g_u3; in2 = g_skip2; outp = g_d2; }
    else { in1 = g_u2; in2 = g_skip1; outp = g_d1; }

    int oc = blockIdx.y;
    int pos = blockIdx.x * blockDim.x + threadIdx.x;
    if (pos >= P) return;
    int oh = pos / WW, ow = pos - oh * WW;

    bool rv[3], cv[3];
    #pragma unroll
    for (int kh = 0; kh < 3; kh++) { int r = oh + kh - 1; rv[kh] = (r >= 0 && r < HH); }
    #pragma unroll
    for (int kw = 0; kw < 3; kw++) { int cc = ow + kw - 1; cv[kw] = (cc >= 0 && cc < WW); }

    const float* wrow = w + (size_t)oc * CTOT * 9;
    float acc[4] = {__ldg(&b[oc]), 0.0f, 0.0f, 0.0f};
    #pragma unroll 4
    for (int ci = 0; ci < CTOT; ci++) {
        const float* src = (C2 == 0 || ci < C1) ? (in1 + (size_t)ci * P)
                                                : (in2 + (size_t)(ci - C1) * P);
        const float* wv = wrow + ci * 9;
        float a = acc[ci & 3];
        #pragma unroll
        for (int kh = 0; kh < 3; kh++) {
            if (!rv[kh]) continue;
            int r = oh + kh - 1;
            #pragma unroll
            for (int kw = 0; kw < 3; kw++) {
                if (!cv[kw]) continue;
                int cc = ow + kw - 1;
                a = __fmaf_rn(__ldg(&src[r * WW + cc]), __ldg(&wv[kh * 3 + kw]), a);
            }
        }
        acc[ci & 3] = a;
    }
    float rres = __fadd_rn(__fadd_rn(acc[0], acc[1]), __fadd_rn(acc[2], acc[3]));
    rres = fmaxf(rres, 0.0f);   // all decoder convs are followed by relu
    outp[(size_t)oc * P + pos] = rres;
}

// ---------------------------------------------------------------------------
// Bilinear upsample (half-pixel centers, edge clamp).
// ---------------------------------------------------------------------------
template<int STAGE, int C, int IHH, int IWW, int OHH, int OWW>
__global__ void upsample_kernel() {
    constexpr int OP = OHH * OWW;
    constexpr int IP = IHH * IWW;
    const float* in;
    float* outp;
    if constexpr (STAGE == 4) { in = g_d4; outp = g_u4; }
    else if constexpr (STAGE == 3) { in = g_d3; outp = g_u3; }
    else if constexpr (STAGE == 2) { in = g_d2; outp = g_u2; }
    else { in = g_d1; outp = g_u1; }

    int idx = blockIdx.x * blockDim.x + threadIdx.x;
    if (idx >= C * OP) return;
    int cch = idx / OP;
    int rem = idx - cch * OP;
    int oh = rem / OWW, ow = rem - oh * OWW;

    float sy = (oh + 0.5f) * ((float)IHH / (float)OHH) - 0.5f;
    float sx = (ow + 0.5f) * ((float)IWW / (float)OWW) - 0.5f;
    float fy = floorf(sy), fx = floorf(sx);
    float wy = sy - fy, wx = sx - fx;
    int y0 = (int)fy, x0 = (int)fx;
    int y0c = max(y0, 0), y1c = min(y0 + 1, IHH - 1);
    int x0c = max(x0, 0), x1c = min(x0 + 1, IWW - 1);

    const float* src = in + (size_t)cch * IP;
    float v00 = __ldg(&src[y0c * IWW + x0c]);
    float v01 = __ldg(&src[y0c * IWW + x1c]);
    float v10 = __ldg(&src[y1c * IWW + x0c]);
    float v11 = __ldg(&src[y1c * IWW + x1c]);
    float top = __fadd_rn(__fmul_rn(1.0f - wx, v00), __fmul_rn(wx, v01));
    float bot = __fadd_rn(__fmul_rn(1.0f - wx, v10), __fmul_rn(wx, v11));
    outp[idx] = __fadd_rn(__fmul_rn(1.0f - wy, top), __fmul_rn(wy, bot));
}

// ---------------------------------------------------------------------------
// Final 1x1 conv: g_u1[8,100,368] -> out[1,100,368]
// ---------------------------------------------------------------------------
__global__ void outconv_kernel(const float* __restrict__ wo,
                               const float* __restrict__ bo,
                               float* __restrict__ out) {
    int pos = blockIdx.x * blockDim.x + threadIdx.x;
    if (pos >= P0) return;
    float acc = __ldg(&bo[0]);
    #pragma unroll
    for (int cch = 0; cch < 8; cch++)
        acc = __fmaf_rn(g_u1[cch * P0 + pos], __ldg(&wo[cch]), acc);
    out[pos] = acc;
}

// ---------------------------------------------------------------------------
// Host launcher: kernel launches ONLY.
// ---------------------------------------------------------------------------
static inline int cdiv(int a, int b) { return (a + b - 1) / b; }

extern "C" void kernel_launch(void* const* d_in, const int* in_sizes, int n_in,
                              void* d_out, int out_size) {
    const float* x   = (const float*)d_in[0];
    const float* w1  = (const float*)d_in[1];
    const float* b1  = (const float*)d_in[2];
    const float* w2  = (const float*)d_in[3];
    const float* b2  = (const float*)d_in[4];
    const float* w3  = (const float*)d_in[5];
    const float* b3  = (const float*)d_in[6];
    const float* w4  = (const float*)d_in[7];
    const float* b4  = (const float*)d_in[8];
    const float* dw4 = (const float*)d_in[9];
    const float* db4 = (const float*)d_in[10];
    const float* dw3 = (const float*)d_in[11];
    const float* db3 = (const float*)d_in[12];
    const float* dw2 = (const float*)d_in[13];
    const float* db2 = (const float*)d_in[14];
    const float* dw1 = (const float*)d_in[15];
    const float* db1 = (const float*)d_in[16];
    const float* wo  = (const float*)d_in[17];
    const float* bo  = (const float*)d_in[18];
    float* out = (float*)d_out;

    // ---- Encoder ----
    fused_l1_kernel<<<cdiv(N1, 128), 128>>>(x, w1, b1);

    convs_kernel<2, 4, 8, H1, W1, H2, W2, 0>
        <<<cdiv(T_STEPS * P2, 128), 128>>>(w2, b2);
    scan_kernel<2, 8, P2, true><<<cdiv(N2, 128), 128>>>();

    convs_kernel<3, 8, 16, H2, W2, H3, W3, 1>
        <<<cdiv(T_STEPS * P3, 128), 128>>>(w3, b3);
    scan_kernel<3, 16, P3, true><<<cdiv(N3, 128), 128>>>();

    convs_kernel<4, 16, 32, H3, W3, H4, W4, 1>
        <<<cdiv(T_STEPS * P4, 128), 128>>>(w4, b4);
    scan_kernel<4, 32, P4, false><<<cdiv(N4, 128), 128>>>();

    // ---- Decoder ----
    {   dim3 grid(1, 64);   // dec4: 640 -> 64 @ 7x23
        dconv_kernel<4, 640, 0, 64, H4, W4><<<grid, 192>>>(dw4, db4);
    }
    upsample_kernel<4, 64, H4, W4, H3, W3><<<cdiv(64 * P3, 256), 256>>>();
    {   dim3 grid(cdiv(P3, 128), 32);   // dec3: 64+320 -> 32 @ 13x46
        dconv_kernel<3, 64, 320, 32, H3, W3><<<grid, 128>>>(dw3, db3);
    }
    upsample_kernel<3, 32, H3, W3, H2, W2><<<cdiv(32 * P2, 256), 256>>>();
    {   dim3 grid(cdiv(P2, 128), 16);   // dec2: 32+160 -> 16 @ 25x92
        dconv_kernel<2, 32, 160, 16, H2, W2><<<grid, 128>>>(dw2, db2);
    }
    upsample_kernel<2, 16, H2, W2, H1, W1><<<cdiv(16 * P1, 256), 256>>>();
    {   dim3 grid(cdiv(P1, 128), 8);    // dec1: 16+80 -> 8 @ 50x184
        dconv_kernel<1, 16, 80, 8, H1, W1><<<grid, 128>>>(dw1, db1);
    }
    upsample_kernel<1, 8, H1, W1, H0, W0><<<cdiv(8 * P0, 256), 256>>>();
    outconv_kernel<<<cdiv(P0, 256), 256>>>(wo, bo, out);
}

// round 11
// speedup vs baseline: 1.1107x; 1.1107x over previous
#include <cuda_runtime.h>
#include <cuda_bf16.h>
#include <cstdint>
#include <cstddef>

// ---------------------------------------------------------------------------
// Constants (total_steps=1000 -> K=10 bins of S=100)
// ---------------------------------------------------------------------------
#define T_STEPS 1000
#define SBIN    100
#define KBINS   10

#define H0 100
#define W0 368
#define H1 50
#define W1 184
#define H2 25
#define W2 92
#define H3 13
#define W3 46
#define H4 7
#define W4 23

#define P0 (H0*W0)   // 36800
#define P1 (H1*W1)   // 9200
#define P2 (H2*W2)   // 2300
#define P3 (H3*W3)   // 598
#define P4 (H4*W4)   // 161

#define N1 (4*P1)    // 36800
#define N2 (8*P2)    // 18400
#define N3 (16*P3)   // 9568
#define N4 (32*P4)   // 5152

// ---------------------------------------------------------------------------
// Scratch (device globals; allocation-free per harness rules).
// Spike buffers are CHANNEL-LAST: s[t][pos][ic] so one conv tap's CIN bytes
// are a single aligned vector load.
// ---------------------------------------------------------------------------
__device__ float         g_c1[(size_t)T_STEPS * N1];
__device__ unsigned char g_s1[(size_t)T_STEPS * N1];
__device__ float         g_c2[(size_t)T_STEPS * N2];
__device__ unsigned char g_s2[(size_t)T_STEPS * N2];
__device__ float         g_c3[(size_t)T_STEPS * N3];
__device__ unsigned char g_s3[(size_t)T_STEPS * N3];
__device__ float         g_c4[(size_t)T_STEPS * N4];

__device__ float g_skip1[80  * P1];
__device__ float g_skip2[160 * P2];
__device__ float g_skip3[320 * P3];
__device__ float g_skip4[640 * P4];

__device__ float g_d4[64 * P4];
__device__ float g_u4[64 * P3];
__device__ float g_d3[32 * P3];
__device__ float g_u3[32 * P2];
__device__ float g_d2[16 * P2];
__device__ float g_u2[16 * P1];
__device__ float g_d1[8  * P1];
__device__ float g_u1[8  * P0];

// Device-side buffer selectors (compile-time)
template<int L> __device__ __forceinline__ float* cbuf_of() {
    if constexpr (L == 1) return g_c1;
    else if constexpr (L == 2) return g_c2;
    else if constexpr (L == 3) return g_c3;
    else return g_c4;
}
template<int L> __device__ __forceinline__ unsigned char* sbuf_of() {
    if constexpr (L == 1) return g_s1;
    else if constexpr (L == 2) return g_s2;
    else return g_s3;
}
template<int L> __device__ __forceinline__ float* skip_of() {
    if constexpr (L == 1) return g_skip1;
    else if constexpr (L == 2) return g_skip2;
    else if constexpr (L == 3) return g_skip3;
    else return g_skip4;
}

// ---------------------------------------------------------------------------
// Layer-1 conv: x[t,1,100,368] -> g_c1[t,4,50,184]  (stride 2, SAME pad_lo=0)
// ---------------------------------------------------------------------------
__global__ void conv1_kernel(const float* __restrict__ x,
                             const float* __restrict__ w1,
                             const float* __restrict__ b1) {
    __shared__ float ws[40];
    if (threadIdx.x < 36) ws[threadIdx.x] = w1[threadIdx.x];
    if (threadIdx.x < 4)  ws[36 + threadIdx.x] = b1[threadIdx.x];
    __syncthreads();

    int idx = blockIdx.x * blockDim.x + threadIdx.x;
    if (idx >= T_STEPS * P1) return;
    int t = idx / P1;
    int pos = idx - t * P1;
    int oh = pos / W1, ow = pos - oh * W1;

    const float* xt = x + (size_t)t * P0;
    float a0 = ws[36], a1 = ws[37], a2 = ws[38], a3 = ws[39];
    #pragma unroll
    for (int kh = 0; kh < 3; kh++) {
        int r = 2 * oh + kh;
        if (r >= H0) continue;
        #pragma unroll
        for (int kw = 0; kw < 3; kw++) {
            int cc = 2 * ow + kw;
            if (cc >= W0) continue;
            float v = __ldg(&xt[r * W0 + cc]);
            int tp = kh * 3 + kw;
            a0 = __fmaf_rn(v, ws[tp],      a0);
            a1 = __fmaf_rn(v, ws[9 + tp],  a1);
            a2 = __fmaf_rn(v, ws[18 + tp], a2);
            a3 = __fmaf_rn(v, ws[27 + tp], a3);
        }
    }
    float* out = g_c1 + (size_t)t * N1 + pos;
    out[0]      = a0;
    out[P1]     = a1;
    out[2 * P1] = a2;
    out[3 * P1] = a3;
}

// ---------------------------------------------------------------------------
// Spike conv (stride 2, SAME) with CHANNEL-LAST spike input:
// one vector load per valid tap (u32 for CIN=4, uint2 for 8, uint4 for 16).
// ---------------------------------------------------------------------------
template<int CIN, int COUT>
__device__ __forceinline__ void tap_accum_word(unsigned int v, const float* ws,
                                               int ic_base, int tap,
                                               float (&acc)[COUT]) {
    #pragma unroll
    for (int j = 0; j < 4 && ic_base + j < CIN; j++) {
        if ((v >> (8 * j)) & 0xffu) {
            const float* wv = &ws[((ic_base + j) * 9 + tap) * COUT];
            #pragma unroll
            for (int o = 0; o < COUT; o++)
                acc[o] = __fadd_rn(acc[o], wv[o]);
        }
    }
}

template<int L, int CIN, int COUT, int IH, int IW, int OH, int OW, int PH>
__global__ void convs_kernel(const float* __restrict__ w,
                             const float* __restrict__ b) {
    constexpr int P  = OH * OW;
    constexpr int NI = CIN * IH * IW;
    constexpr int NW = CIN * 9 * COUT;
    const unsigned char* __restrict__ spk = sbuf_of<L - 1>();
    float* __restrict__ cbuf = cbuf_of<L>();

    __shared__ __align__(16) float ws[NW];
    __shared__ float bs[COUT];
    for (int i = threadIdx.x; i < NW; i += blockDim.x) {
        int oc = i / (CIN * 9);
        int j  = i - oc * (CIN * 9);        // ic*9 + tap
        ws[j * COUT + oc] = w[i];
    }
    for (int i = threadIdx.x; i < COUT; i += blockDim.x) bs[i] = b[i];
    __syncthreads();

    int idx = blockIdx.x * blockDim.x + threadIdx.x;
    if (idx >= T_STEPS * P) return;
    int t = idx / P;
    int pos = idx - t * P;
    int oh = pos / OW, ow = pos - oh * OW;

    float acc[COUT];
    #pragma unroll
    for (int o = 0; o < COUT; o++) acc[o] = bs[o];

    const unsigned char* sp = spk + (size_t)t * NI;
    #pragma unroll
    for (int kh = 0; kh < 3; kh++) {
        int r = 2 * oh + kh - PH;
        if (r < 0 || r >= IH) continue;
        #pragma unroll
        for (int kw = 0; kw < 3; kw++) {
            int cc = 2 * ow + kw;
            if (cc >= IW) continue;
            int tap = kh * 3 + kw;
            const unsigned char* p = sp + (size_t)(r * IW + cc) * CIN;
            if constexpr (CIN == 4) {
                unsigned int v = __ldg((const unsigned int*)p);
                tap_accum_word<CIN, COUT>(v, ws, 0, tap, acc);
            } else if constexpr (CIN == 8) {
                uint2 v = __ldg((const uint2*)p);
                tap_accum_word<CIN, COUT>(v.x, ws, 0, tap, acc);
                tap_accum_word<CIN, COUT>(v.y, ws, 4, tap, acc);
            } else {  // CIN == 16
                uint4 v = __ldg((const uint4*)p);
                tap_accum_word<CIN, COUT>(v.x, ws, 0,  tap, acc);
                tap_accum_word<CIN, COUT>(v.y, ws, 4,  tap, acc);
                tap_accum_word<CIN, COUT>(v.z, ws, 8,  tap, acc);
                tap_accum_word<CIN, COUT>(v.w, ws, 12, tap, acc);
            }
        }
    }
    float* out = cbuf + (size_t)t * (COUT * P) + pos;
    #pragma unroll
    for (int o = 0; o < COUT; o++) out[o * P] = acc[o];
}

// ---------------------------------------------------------------------------
// Per-neuron membrane scan, spill-free (UF=25, A/B named buffers, compile-time
// selection). Branchless reset: u = m-1; m = (u>0) ? u : m  -- exactly
// equivalent to the predicated version (sign(m-1)==(m>1) in RN; reset value
// IS m-1), but uses pred-as-data SEL (4cyc) instead of pred-guard (13cyc).
// Spike store is CHANNEL-LAST: sb = base + pos*C + c, stride N per timestep.
// ---------------------------------------------------------------------------
template<int N, bool WRITE_S>
__device__ __forceinline__ void scan_group(const float* __restrict__ cp,
                                           unsigned char* __restrict__ sb,
                                           int tproc,
                                           float (&proc)[25], float (&pre)[25],
                                           float& m, float& sum, float& sq) {
    const int tpre = tproc + 25;
    if (tpre < T_STEPS) {
        #pragma unroll
        for (int j = 0; j < 25; j++)
            pre[j] = __ldg(cp + (size_t)(tpre + j) * N);
    }
    #pragma unroll
    for (int j = 0; j < 25; j++) {
        // exact mul-then-add mirrors BETA*m + conv
        m = __fadd_rn(__fmul_rn(0.9f, m), proc[j]);
        float u = __fadd_rn(m, -1.0f);
        bool spk = (u > 0.0f);
        if (WRITE_S)
            sb[(size_t)(tproc + j) * N] = spk ? (unsigned char)1
                                              : (unsigned char)0;
        m = spk ? u : m;                    // soft reset (exact)
        sum = __fadd_rn(sum, m);
        sq  = __fmaf_rn(m, m, sq);
    }
}

template<int L, int C, int P, bool WRITE_S>
__global__ void scan_kernel() {
    constexpr int N = C * P;
    const float* __restrict__ cbuf = cbuf_of<L>();
    float* __restrict__ skip = skip_of<L>();

    int n = blockIdx.x * blockDim.x + threadIdx.x;
    if (n >= N) return;
    int c = n / P, pos = n - c * P;

    const float* cp = cbuf + n;
    unsigned char* sb = (unsigned char*)0;
    if (WRITE_S) sb = sbuf_of<L>() + (size_t)pos * C + c;   // channel-last

    float A[25], B[25];
    #pragma unroll
    for (int j = 0; j < 25; j++) A[j] = __ldg(cp + (size_t)j * N);

    float m = 0.0f;
    int t = 0;
    for (int k = 0; k < KBINS; k++) {
        float sum = 0.0f, sq = 0.0f;
        scan_group<N, WRITE_S>(cp, sb, t, A, B, m, sum, sq); t += 25;
        scan_group<N, WRITE_S>(cp, sb, t, B, A, m, sum, sq); t += 25;
        scan_group<N, WRITE_S>(cp, sb, t, A, B, m, sum, sq); t += 25;
        scan_group<N, WRITE_S>(cp, sb, t, B, A, m, sum, sq); t += 25;

        float mu  = __fdiv_rn(sum, (float)SBIN);
        float var = __fsub_rn(__fdiv_rn(sq, (float)SBIN), __fmul_rn(mu, mu));
        float sd  = __fsqrt_rn(fmaxf(var, 1e-8f));
        skip[(size_t)(k * 2 * C + c) * P + pos]     = mu;
        skip[(size_t)(k * 2 * C + C + c) * P + pos] = sd;
    }
}

// ---------------------------------------------------------------------------
// Decoder conv: stride 1, SAME (pad 1), input = concat(in1[C1], in2[C2]).
// ---------------------------------------------------------------------------
template<int STAGE, int C1, int C2, int COUT, int HH, int WW>
__global__ void dconv_kernel(const float* __restrict__ w,
                             const float* __restrict__ b) {
    constexpr int P = HH * WW;
    constexpr int CTOT = C1 + C2;
    const float* in1;
    const float* in2;
    float* outp;
    if constexpr (STAGE == 4) { in1 = g_skip4; in2 = nullptr; outp = g_d4; }
    else if constexpr (STAGE == 3) { in1 = g_u4; in2 = g_skip3; outp = g_d3; }
    else if constexpr (STAGE == 2) { in1 = g_u3; in2 = g_skip2; outp = g_d2; }
    else { in1 = g_u2; in2 = g_skip1; outp = g_d1; }

    int oc = blockIdx.y;
    int pos = blockIdx.x * blockDim.x + threadIdx.x;
    if (pos >= P) return;
    int oh = pos / WW, ow = pos - oh * WW;

    bool rv[3], cv[3];
    #pragma unroll
    for (int kh = 0; kh < 3; kh++) { int r = oh + kh - 1; rv[kh] = (r >= 0 && r < HH); }
    #pragma unroll
    for (int kw = 0; kw < 3; kw++) { int cc = ow + kw - 1; cv[kw] = (cc >= 0 && cc < WW); }

    const float* wrow = w + (size_t)oc * CTOT * 9;
    float acc[4] = {__ldg(&b[oc]), 0.0f, 0.0f, 0.0f};
    #pragma unroll 4
    for (int ci = 0; ci < CTOT; ci++) {
        const float* src = (C2 == 0 || ci < C1) ? (in1 + (size_t)ci * P)
                                                : (in2 + (size_t)(ci - C1) * P);
        const float* wv = wrow + ci * 9;
        float a = acc[ci & 3];
        #pragma unroll
        for (int kh = 0; kh < 3; kh++) {
            if (!rv[kh]) continue;
            int r = oh + kh - 1;
            #pragma unroll
            for (int kw = 0; kw < 3; kw++) {
                if (!cv[kw]) continue;
                int cc = ow + kw - 1;
                a = __fmaf_rn(__ldg(&src[r * WW + cc]), __ldg(&wv[kh * 3 + kw]), a);
            }
        }
        acc[ci & 3] = a;
    }
    float rres = __fadd_rn(__fadd_rn(acc[0], acc[1]), __fadd_rn(acc[2], acc[3]));
    rres = fmaxf(rres, 0.0f);   // all decoder convs are followed by relu
    outp[(size_t)oc * P + pos] = rres;
}

// ---------------------------------------------------------------------------
// Bilinear upsample (half-pixel centers, edge clamp).
// ---------------------------------------------------------------------------
template<int STAGE, int C, int IHH, int IWW, int OHH, int OWW>
__global__ void upsample_kernel() {
    constexpr int OP = OHH * OWW;
    constexpr int IP = IHH * IWW;
    const float* in;
    float* outp;
    if constexpr (STAGE == 4) { in = g_d4; outp = g_u4; }
    else if constexpr (STAGE == 3) { in = g_d3; outp = g_u3; }
    else if constexpr (STAGE == 2) { in = g_d2; outp = g_u2; }
    else { in = g_d1; outp = g_u1; }

    int idx = blockIdx.x * blockDim.x + threadIdx.x;
    if (idx >= C * OP) return;
    int cch = idx / OP;
    int rem = idx - cch * OP;
    int oh = rem / OWW, ow = rem - oh * OWW;

    float sy = (oh + 0.5f) * ((float)IHH / (float)OHH) - 0.5f;
    float sx = (ow + 0.5f) * ((float)IWW / (float)OWW) - 0.5f;
    float fy = floorf(sy), fx = floorf(sx);
    float wy = sy - fy, wx = sx - fx;
    int y0 = (int)fy, x0 = (int)fx;
    int y0c = max(y0, 0), y1c = min(y0 + 1, IHH - 1);
    int x0c = max(x0, 0), x1c = min(x0 + 1, IWW - 1);

    const float* src = in + (size_t)cch * IP;
    float v00 = __ldg(&src[y0c * IWW + x0c]);
    float v01 = __ldg(&src[y0c * IWW + x1c]);
    float v10 = __ldg(&src[y1c * IWW + x0c]);
    float v11 = __ldg(&src[y1c * IWW + x1c]);
    float top = __fadd_rn(__fmul_rn(1.0f - wx, v00), __fmul_rn(wx, v01));
    float bot = __fadd_rn(__fmul_rn(1.0f - wx, v10), __fmul_rn(wx, v11));
    outp[idx] = __fadd_rn(__fmul_rn(1.0f - wy, top), __fmul_rn(wy, bot));
}

// ---------------------------------------------------------------------------
// Final 1x1 conv: g_u1[8,100,368] -> out[1,100,368]
// ---------------------------------------------------------------------------
__global__ void outconv_kernel(const float* __restrict__ wo,
                               const float* __restrict__ bo,
                               float* __restrict__ out) {
    int pos = blockIdx.x * blockDim.x + threadIdx.x;
    if (pos >= P0) return;
    float acc = __ldg(&bo[0]);
    #pragma unroll
    for (int cch = 0; cch < 8; cch++)
        acc = __fmaf_rn(g_u1[cch * P0 + pos], __ldg(&wo[cch]), acc);
    out[pos] = acc;
}

// ---------------------------------------------------------------------------
// Host launcher: kernel launches ONLY.
// ---------------------------------------------------------------------------
static inline int cdiv(int a, int b) { return (a + b - 1) / b; }

extern "C" void kernel_launch(void* const* d_in, const int* in_sizes, int n_in,
                              void* d_out, int out_size) {
    const float* x   = (const float*)d_in[0];
    const float* w1  = (const float*)d_in[1];
    const float* b1  = (const float*)d_in[2];
    const float* w2  = (const float*)d_in[3];
    const float* b2  = (const float*)d_in[4];
    const float* w3  = (const float*)d_in[5];
    const float* b3  = (const float*)d_in[6];
    const float* w4  = (const float*)d_in[7];
    const float* b4  = (const float*)d_in[8];
    const float* dw4 = (const float*)d_in[9];
    const float* db4 = (const float*)d_in[10];
    const float* dw3 = (const float*)d_in[11];
    const float* db3 = (const float*)d_in[12];
    const float* dw2 = (const float*)d_in[13];
    const float* db2 = (const float*)d_in[14];
    const float* dw1 = (const float*)d_in[15];
    const float* db1 = (const float*)d_in[16];
    const float* wo  = (const float*)d_in[17];
    const float* bo  = (const float*)d_in[18];
    float* out = (float*)d_out;

    // ---- Encoder: alternating batched conv / per-neuron scan ----
    conv1_kernel<<<cdiv(T_STEPS * P1, 256), 256>>>(x, w1, b1);
    scan_kernel<1, 4, P1, true><<<cdiv(N1, 128), 128>>>();

    convs_kernel<2, 4, 8, H1, W1, H2, W2, 0>
        <<<cdiv(T_STEPS * P2, 128), 128>>>(w2, b2);
    scan_kernel<2, 8, P2, true><<<cdiv(N2, 128), 128>>>();

    convs_kernel<3, 8, 16, H2, W2, H3, W3, 1>
        <<<cdiv(T_STEPS * P3, 128), 128>>>(w3, b3);
    scan_kernel<3, 16, P3, true><<<cdiv(N3, 128), 128>>>();

    convs_kernel<4, 16, 32, H3, W3, H4, W4, 1>
        <<<cdiv(T_STEPS * P4, 128), 128>>>(w4, b4);
    scan_kernel<4, 32, P4, false><<<cdiv(N4, 128), 128>>>();

    // ---- Decoder ----
    {   dim3 grid(1, 64);   // dec4: 640 -> 64 @ 7x23
        dconv_kernel<4, 640, 0, 64, H4, W4><<<grid, 192>>>(dw4, db4);
    }
    upsample_kernel<4, 64, H4, W4, H3, W3><<<cdiv(64 * P3, 256), 256>>>();
    {   dim3 grid(cdiv(P3, 128), 32);   // dec3: 64+320 -> 32 @ 13x46
        dconv_kernel<3, 64, 320, 32, H3, W3><<<grid, 128>>>(dw3, db3);
    }
    upsample_kernel<3, 32, H3, W3, H2, W2><<<cdiv(32 * P2, 256), 256>>>();
    {   dim3 grid(cdiv(P2, 128), 16);   // dec2: 32+160 -> 16 @ 25x92
        dconv_kernel<2, 32, 160, 16, H2, W2><<<grid, 128>>>(dw2, db2);
    }
    upsample_kernel<2, 16, H2, W2, H1, W1><<<cdiv(16 * P1, 256), 256>>>();
    {   dim3 grid(cdiv(P1, 128), 8);    // dec1: 16+80 -> 8 @ 50x184
        dconv_kernel<1, 16, 80, 8, H1, W1><<<grid, 128>>>(dw1, db1);
    }
    upsample_kernel<1, 8, H1, W1, H0, W0><<<cdiv(8 * P0, 256), 256>>>();
    outconv_kernel<<<cdiv(P0, 256), 256>>>(wo, bo, out);
}

// round 12
// speedup vs baseline: 1.2048x; 1.0848x over previous
#include <cuda_runtime.h>
#include <cuda_bf16.h>
#include <cstdint>
#include <cstddef>

// ---------------------------------------------------------------------------
// Constants (total_steps=1000 -> K=10 bins of S=100)
// ---------------------------------------------------------------------------
#define T_STEPS 1000
#define SBIN    100
#define KBINS   10

#define H0 100
#define W0 368
#define H1 50
#define W1 184
#define H2 25
#define W2 92
#define H3 13
#define W3 46
#define H4 7
#define W4 23

#define P0 (H0*W0)   // 36800
#define P1 (H1*W1)   // 9200
#define P2 (H2*W2)   // 2300
#define P3 (H3*W3)   // 598
#define P4 (H4*W4)   // 161

#define N1 (4*P1)    // 36800
#define N2 (8*P2)    // 18400
#define N3 (16*P3)   // 9568
#define N4 (32*P4)   // 5152

// ---------------------------------------------------------------------------
// Scratch (device globals). EVERYTHING time-indexed is CHANNEL-LAST:
//   currents c[t][pos][oc], spikes s[t][pos][ic].
// Conv writes contiguous float4 vectors; scan threads n' = pos*C + c make
// both the current read (t*N + n') and spike write (t*N + n') coalesced.
// ---------------------------------------------------------------------------
__device__ float         g_c1[(size_t)T_STEPS * N1];
__device__ unsigned char g_s1[(size_t)T_STEPS * N1];
__device__ float         g_c2[(size_t)T_STEPS * N2];
__device__ unsigned char g_s2[(size_t)T_STEPS * N2];
__device__ float         g_c3[(size_t)T_STEPS * N3];
__device__ unsigned char g_s3[(size_t)T_STEPS * N3];
__device__ float         g_c4[(size_t)T_STEPS * N4];

__device__ float g_skip1[80  * P1];
__device__ float g_skip2[160 * P2];
__device__ float g_skip3[320 * P3];
__device__ float g_skip4[640 * P4];

__device__ float g_d4[64 * P4];
__device__ float g_u4[64 * P3];
__device__ float g_d3[32 * P3];
__device__ float g_u3[32 * P2];
__device__ float g_d2[16 * P2];
__device__ float g_u2[16 * P1];
__device__ float g_d1[8  * P1];
__device__ float g_u1[8  * P0];

// Device-side buffer selectors (compile-time)
template<int L> __device__ __forceinline__ float* cbuf_of() {
    if constexpr (L == 1) return g_c1;
    else if constexpr (L == 2) return g_c2;
    else if constexpr (L == 3) return g_c3;
    else return g_c4;
}
template<int L> __device__ __forceinline__ unsigned char* sbuf_of() {
    if constexpr (L == 1) return g_s1;
    else if constexpr (L == 2) return g_s2;
    else return g_s3;
}
template<int L> __device__ __forceinline__ float* skip_of() {
    if constexpr (L == 1) return g_skip1;
    else if constexpr (L == 2) return g_skip2;
    else if constexpr (L == 3) return g_skip3;
    else return g_skip4;
}

// ---------------------------------------------------------------------------
// Layer-1 conv: x[t,1,100,368] -> c1[t][pos][4]  (stride 2, SAME pad_lo=0)
// Channel-last output: one float4 store.
// ---------------------------------------------------------------------------
__global__ void conv1_kernel(const float* __restrict__ x,
                             const float* __restrict__ w1,
                             const float* __restrict__ b1) {
    __shared__ float ws[40];
    if (threadIdx.x < 36) ws[threadIdx.x] = w1[threadIdx.x];
    if (threadIdx.x < 4)  ws[36 + threadIdx.x] = b1[threadIdx.x];
    __syncthreads();

    int idx = blockIdx.x * blockDim.x + threadIdx.x;
    if (idx >= T_STEPS * P1) return;
    int t = idx / P1;
    int pos = idx - t * P1;
    int oh = pos / W1, ow = pos - oh * W1;

    const float* xt = x + (size_t)t * P0;
    float a0 = ws[36], a1 = ws[37], a2 = ws[38], a3 = ws[39];
    #pragma unroll
    for (int kh = 0; kh < 3; kh++) {
        int r = 2 * oh + kh;
        if (r >= H0) continue;
        #pragma unroll
        for (int kw = 0; kw < 3; kw++) {
            int cc = 2 * ow + kw;
            if (cc >= W0) continue;
            float v = __ldg(&xt[r * W0 + cc]);
            int tp = kh * 3 + kw;
            a0 = __fmaf_rn(v, ws[tp],      a0);
            a1 = __fmaf_rn(v, ws[9 + tp],  a1);
            a2 = __fmaf_rn(v, ws[18 + tp], a2);
            a3 = __fmaf_rn(v, ws[27 + tp], a3);
        }
    }
    *(float4*)(g_c1 + ((size_t)t * P1 + pos) * 4) = make_float4(a0, a1, a2, a3);
}

// ---------------------------------------------------------------------------
// Spike conv (stride 2, SAME), channel-last in AND out:
// one vector spike load per tap; COUT accumulators stored as float4 vectors.
// ---------------------------------------------------------------------------
template<int CIN, int COUT>
__device__ __forceinline__ void tap_accum_word(unsigned int v, const float* ws,
                                               int ic_base, int tap,
                                               float (&acc)[COUT]) {
    #pragma unroll
    for (int j = 0; j < 4 && ic_base + j < CIN; j++) {
        if ((v >> (8 * j)) & 0xffu) {
            const float* wv = &ws[((ic_base + j) * 9 + tap) * COUT];
            #pragma unroll
            for (int o = 0; o < COUT; o++)
                acc[o] = __fadd_rn(acc[o], wv[o]);
        }
    }
}

template<int L, int CIN, int COUT, int IH, int IW, int OH, int OW, int PH>
__global__ void convs_kernel(const float* __restrict__ w,
                             const float* __restrict__ b) {
    constexpr int P  = OH * OW;
    constexpr int NI = CIN * IH * IW;
    constexpr int NW = CIN * 9 * COUT;
    const unsigned char* __restrict__ spk = sbuf_of<L - 1>();
    float* __restrict__ cbuf = cbuf_of<L>();

    __shared__ __align__(16) float ws[NW];
    __shared__ float bs[COUT];
    for (int i = threadIdx.x; i < NW; i += blockDim.x) {
        int oc = i / (CIN * 9);
        int j  = i - oc * (CIN * 9);        // ic*9 + tap
        ws[j * COUT + oc] = w[i];
    }
    for (int i = threadIdx.x; i < COUT; i += blockDim.x) bs[i] = b[i];
    __syncthreads();

    int idx = blockIdx.x * blockDim.x + threadIdx.x;
    if (idx >= T_STEPS * P) return;
    int t = idx / P;
    int pos = idx - t * P;
    int oh = pos / OW, ow = pos - oh * OW;

    float acc[COUT];
    #pragma unroll
    for (int o = 0; o < COUT; o++) acc[o] = bs[o];

    const unsigned char* sp = spk + (size_t)t * NI;
    #pragma unroll
    for (int kh = 0; kh < 3; kh++) {
        int r = 2 * oh + kh - PH;
        if (r < 0 || r >= IH) continue;
        #pragma unroll
        for (int kw = 0; kw < 3; kw++) {
            int cc = 2 * ow + kw;
            if (cc >= IW) continue;
            int tap = kh * 3 + kw;
            const unsigned char* p = sp + (size_t)(r * IW + cc) * CIN;
            if constexpr (CIN == 4) {
                unsigned int v = __ldg((const unsigned int*)p);
                tap_accum_word<CIN, COUT>(v, ws, 0, tap, acc);
            } else if constexpr (CIN == 8) {
                uint2 v = __ldg((const uint2*)p);
                tap_accum_word<CIN, COUT>(v.x, ws, 0, tap, acc);
                tap_accum_word<CIN, COUT>(v.y, ws, 4, tap, acc);
            } else {  // CIN == 16
                uint4 v = __ldg((const uint4*)p);
                tap_accum_word<CIN, COUT>(v.x, ws, 0,  tap, acc);
                tap_accum_word<CIN, COUT>(v.y, ws, 4,  tap, acc);
                tap_accum_word<CIN, COUT>(v.z, ws, 8,  tap, acc);
                tap_accum_word<CIN, COUT>(v.w, ws, 12, tap, acc);
            }
        }
    }
    float4* out = (float4*)(cbuf + ((size_t)t * P + pos) * COUT);
    #pragma unroll
    for (int o = 0; o < COUT / 4; o++)
        out[o] = make_float4(acc[4 * o], acc[4 * o + 1],
                             acc[4 * o + 2], acc[4 * o + 3]);
}

// ---------------------------------------------------------------------------
// Per-neuron membrane scan, channel-last mapping: thread n' = pos*C + c.
// Current read and spike write are both at (t*N + n') -> fully coalesced.
// UF=50 deep A/B register prefetch (compile-time selection; ~140 regs, no
// occupancy cost at 4 warps/SM) to double bytes-in-flight vs UF=25.
// Branchless exact reset: u = m-1; m = (u>0) ? u : m.
// ---------------------------------------------------------------------------
#define UF 50

template<int N, bool WRITE_S>
__device__ __forceinline__ void scan_group(const float* __restrict__ cp,
                                           unsigned char* __restrict__ sb,
                                           int tproc,
                                           float (&proc)[UF], float (&pre)[UF],
                                           float& m, float& sum, float& sq) {
    const int tpre = tproc + UF;
    if (tpre < T_STEPS) {
        #pragma unroll
        for (int j = 0; j < UF; j++)
            pre[j] = __ldg(cp + (size_t)(tpre + j) * N);
    }
    #pragma unroll
    for (int j = 0; j < UF; j++) {
        // exact mul-then-add mirrors BETA*m + conv
        m = __fadd_rn(__fmul_rn(0.9f, m), proc[j]);
        float u = __fadd_rn(m, -1.0f);
        bool spk = (u > 0.0f);
        if (WRITE_S)
            sb[(size_t)(tproc + j) * N] = spk ? (unsigned char)1
                                              : (unsigned char)0;
        m = spk ? u : m;                    // soft reset (exact)
        sum = __fadd_rn(sum, m);
        sq  = __fmaf_rn(m, m, sq);
    }
}

template<int L, int C, int P, bool WRITE_S>
__global__ void scan_kernel() {
    constexpr int N = C * P;
    const float* __restrict__ cbuf = cbuf_of<L>();
    float* __restrict__ skip = skip_of<L>();

    int n = blockIdx.x * blockDim.x + threadIdx.x;   // n = pos*C + c
    if (n >= N) return;
    int pos = n / C, c = n - pos * C;

    const float* cp = cbuf + n;
    unsigned char* sb = (unsigned char*)0;
    if (WRITE_S) sb = sbuf_of<L>() + n;

    float A[UF], B[UF];
    #pragma unroll
    for (int j = 0; j < UF; j++) A[j] = __ldg(cp + (size_t)j * N);

    float m = 0.0f;
    int t = 0;
    for (int k = 0; k < KBINS; k++) {
        float sum = 0.0f, sq = 0.0f;
        scan_group<N, WRITE_S>(cp, sb, t, A, B, m, sum, sq); t += UF;
        scan_group<N, WRITE_S>(cp, sb, t, B, A, m, sum, sq); t += UF;

        float mu  = __fdiv_rn(sum, (float)SBIN);
        float var = __fsub_rn(__fdiv_rn(sq, (float)SBIN), __fmul_rn(mu, mu));
        float sd  = __fsqrt_rn(fmaxf(var, 1e-8f));
        skip[(size_t)(k * 2 * C + c) * P + pos]     = mu;
        skip[(size_t)(k * 2 * C + C + c) * P + pos] = sd;
    }
}

// ---------------------------------------------------------------------------
// Decoder conv: stride 1, SAME (pad 1), input = concat(in1[C1], in2[C2]).
// ---------------------------------------------------------------------------
template<int STAGE, int C1, int C2, int COUT, int HH, int WW>
__global__ void dconv_kernel(const float* __restrict__ w,
                             const float* __restrict__ b) {
    constexpr int P = HH * WW;
    constexpr int CTOT = C1 + C2;
    const float* in1;
    const float* in2;
    float* outp;
    if constexpr (STAGE == 4) { in1 = g_skip4; in2 = nullptr; outp = g_d4; }
    else if constexpr (STAGE == 3) { in1 = g_u4; in2 = g_skip3; outp = g_d3; }
    else if constexpr (STAGE == 2) { in1 = g_u3; in2 = g_skip2; outp = g_d2; }
    else { in1 = g_u2; in2 = g_skip1; outp = g_d1; }

    int oc = blockIdx.y;
    int pos = blockIdx.x * blockDim.x + threadIdx.x;
    if (pos >= P) return;
    int oh = pos / WW, ow = pos - oh * WW;

    bool rv[3], cv[3];
    #pragma unroll
    for (int kh = 0; kh < 3; kh++) { int r = oh + kh - 1; rv[kh] = (r >= 0 && r < HH); }
    #pragma unroll
    for (int kw = 0; kw < 3; kw++) { int cc = ow + kw - 1; cv[kw] = (cc >= 0 && cc < WW); }

    const float* wrow = w + (size_t)oc * CTOT * 9;
    float acc[4] = {__ldg(&b[oc]), 0.0f, 0.0f, 0.0f};
    #pragma unroll 4
    for (int ci = 0; ci < CTOT; ci++) {
        const float* src = (C2 == 0 || ci < C1) ? (in1 + (size_t)ci * P)
                                                : (in2 + (size_t)(ci - C1) * P);
        const float* wv = wrow + ci * 9;
        float a = acc[ci & 3];
        #pragma unroll
        for (int kh = 0; kh < 3; kh++) {
            if (!rv[kh]) continue;
            int r = oh + kh - 1;
            #pragma unroll
            for (int kw = 0; kw < 3; kw++) {
                if (!cv[kw]) continue;
                int cc = ow + kw - 1;
                a = __fmaf_rn(__ldg(&src[r * WW + cc]), __ldg(&wv[kh * 3 + kw]), a);
            }
        }
        acc[ci & 3] = a;
    }
    float rres = __fadd_rn(__fadd_rn(acc[0], acc[1]), __fadd_rn(acc[2], acc[3]));
    rres = fmaxf(rres, 0.0f);   // all decoder convs are followed by relu
    outp[(size_t)oc * P + pos] = rres;
}

// ---------------------------------------------------------------------------
// Bilinear upsample (half-pixel centers, edge clamp).
// ---------------------------------------------------------------------------
template<int STAGE, int C, int IHH, int IWW, int OHH, int OWW>
__global__ void upsample_kernel() {
    constexpr int OP = OHH * OWW;
    constexpr int IP = IHH * IWW;
    const float* in;
    float* outp;
    if constexpr (STAGE == 4) { in = g_d4; outp = g_u4; }
    else if constexpr (STAGE == 3) { in = g_d3; outp = g_u3; }
    else if constexpr (STAGE == 2) { in = g_d2; outp = g_u2; }
    else { in = g_d1; outp = g_u1; }

    int idx = blockIdx.x * blockDim.x + threadIdx.x;
    if (idx >= C * OP) return;
    int cch = idx / OP;
    int rem = idx - cch * OP;
    int oh = rem / OWW, ow = rem - oh * OWW;

    float sy = (oh + 0.5f) * ((float)IHH / (float)OHH) - 0.5f;
    float sx = (ow + 0.5f) * ((float)IWW / (float)OWW) - 0.5f;
    float fy = floorf(sy), fx = floorf(sx);
    float wy = sy - fy, wx = sx - fx;
    int y0 = (int)fy, x0 = (int)fx;
    int y0c = max(y0, 0), y1c = min(y0 + 1, IHH - 1);
    int x0c = max(x0, 0), x1c = min(x0 + 1, IWW - 1);

    const float* src = in + (size_t)cch * IP;
    float v00 = __ldg(&src[y0c * IWW + x0c]);
    float v01 = __ldg(&src[y0c * IWW + x1c]);
    float v10 = __ldg(&src[y1c * IWW + x0c]);
    float v11 = __ldg(&src[y1c * IWW + x1c]);
    float top = __fadd_rn(__fmul_rn(1.0f - wx, v00), __fmul_rn(wx, v01));
    float bot = __fadd_rn(__fmul_rn(1.0f - wx, v10), __fmul_rn(wx, v11));
    outp[idx] = __fadd_rn(__fmul_rn(1.0f - wy, top), __fmul_rn(wy, bot));
}

// ---------------------------------------------------------------------------
// Final 1x1 conv: g_u1[8,100,368] -> out[1,100,368]
// ---------------------------------------------------------------------------
__global__ void outconv_kernel(const float* __restrict__ wo,
                               const float* __restrict__ bo,
                               float* __restrict__ out) {
    int pos = blockIdx.x * blockDim.x + threadIdx.x;
    if (pos >= P0) return;
    float acc = __ldg(&bo[0]);
    #pragma unroll
    for (int cch = 0; cch < 8; cch++)
        acc = __fmaf_rn(g_u1[cch * P0 + pos], __ldg(&wo[cch]), acc);
    out[pos] = acc;
}

// ---------------------------------------------------------------------------
// Host launcher: kernel launches ONLY.
// ---------------------------------------------------------------------------
static inline int cdiv(int a, int b) { return (a + b - 1) / b; }

extern "C" void kernel_launch(void* const* d_in, const int* in_sizes, int n_in,
                              void* d_out, int out_size) {
    const float* x   = (const float*)d_in[0];
    const float* w1  = (const float*)d_in[1];
    const float* b1  = (const float*)d_in[2];
    const float* w2  = (const float*)d_in[3];
    const float* b2  = (const float*)d_in[4];
    const float* w3  = (const float*)d_in[5];
    const float* b3  = (const float*)d_in[6];
    const float* w4  = (const float*)d_in[7];
    const float* b4  = (const float*)d_in[8];
    const float* dw4 = (const float*)d_in[9];
    const float* db4 = (const float*)d_in[10];
    const float* dw3 = (const float*)d_in[11];
    const float* db3 = (const float*)d_in[12];
    const float* dw2 = (const float*)d_in[13];
    const float* db2 = (const float*)d_in[14];
    const float* dw1 = (const float*)d_in[15];
    const float* db1 = (const float*)d_in[16];
    const float* wo  = (const float*)d_in[17];
    const float* bo  = (const float*)d_in[18];
    float* out = (float*)d_out;

    // ---- Encoder: alternating batched conv / per-neuron scan ----
    conv1_kernel<<<cdiv(T_STEPS * P1, 256), 256>>>(x, w1, b1);
    scan_kernel<1, 4, P1, true><<<cdiv(N1, 128), 128>>>();

    convs_kernel<2, 4, 8, H1, W1, H2, W2, 0>
        <<<cdiv(T_STEPS * P2, 128), 128>>>(w2, b2);
    scan_kernel<2, 8, P2, true><<<cdiv(N2, 128), 128>>>();

    convs_kernel<3, 8, 16, H2, W2, H3, W3, 1>
        <<<cdiv(T_STEPS * P3, 128), 128>>>(w3, b3);
    scan_kernel<3, 16, P3, true><<<cdiv(N3, 128), 128>>>();

    convs_kernel<4, 16, 32, H3, W3, H4, W4, 1>
        <<<cdiv(T_STEPS * P4, 128), 128>>>(w4, b4);
    scan_kernel<4, 32, P4, false><<<cdiv(N4, 128), 128>>>();

    // ---- Decoder ----
    {   dim3 grid(1, 64);   // dec4: 640 -> 64 @ 7x23
        dconv_kernel<4, 640, 0, 64, H4, W4><<<grid, 192>>>(dw4, db4);
    }
    upsample_kernel<4, 64, H4, W4, H3, W3><<<cdiv(64 * P3, 256), 256>>>();
    {   dim3 grid(cdiv(P3, 128), 32);   // dec3: 64+320 -> 32 @ 13x46
        dconv_kernel<3, 64, 320, 32, H3, W3><<<grid, 128>>>(dw3, db3);
    }
    upsample_kernel<3, 32, H3, W3, H2, W2><<<cdiv(32 * P2, 256), 256>>>();
    {   dim3 grid(cdiv(P2, 128), 16);   // dec2: 32+160 -> 16 @ 25x92
        dconv_kernel<2, 32, 160, 16, H2, W2><<<grid, 128>>>(dw2, db2);
    }
    upsample_kernel<2, 16, H2, W2, H1, W1><<<cdiv(16 * P1, 256), 256>>>();
    {   dim3 grid(cdiv(P1, 128), 8);    // dec1: 16+80 -> 8 @ 50x184
        dconv_kernel<1, 16, 80, 8, H1, W1><<<grid, 128>>>(dw1, db1);
    }
    upsample_kernel<1, 8, H1, W1, H0, W0><<<cdiv(8 * P0, 256), 256>>>();
    outconv_kernel<<<cdiv(P0, 256), 256>>>(wo, bo, out);
}

// round 13
// speedup vs baseline: 1.3031x; 1.0815x over previous
#include <cuda_runtime.h>
#include <cuda_bf16.h>
#include <cstdint>
#include <cstddef>

// ---------------------------------------------------------------------------
// Constants (total_steps=1000 -> K=10 bins of S=100)
// ---------------------------------------------------------------------------
#define T_STEPS 1000
#define SBIN    100
#define KBINS   10

#define H0 100
#define W0 368
#define H1 50
#define W1 184
#define H2 25
#define W2 92
#define H3 13
#define W3 46
#define H4 7
#define W4 23

#define P0 (H0*W0)   // 36800
#define P1 (H1*W1)   // 9200
#define P2 (H2*W2)   // 2300
#define P3 (H3*W3)   // 598
#define P4 (H4*W4)   // 161

#define N1 (4*P1)    // 36800
#define N2 (8*P2)    // 18400
#define N3 (16*P3)   // 9568
#define N4 (32*P4)   // 5152

// ---------------------------------------------------------------------------
// Scratch (device globals). Time-indexed data is CHANNEL-LAST:
//   currents c[t][pos][oc], spikes s[t][pos][ic].
// Layer 1 currents are never materialized (fused conv+scan).
// ---------------------------------------------------------------------------
__device__ unsigned char g_s1[(size_t)T_STEPS * N1];
__device__ float         g_c2[(size_t)T_STEPS * N2];
__device__ unsigned char g_s2[(size_t)T_STEPS * N2];
__device__ float         g_c3[(size_t)T_STEPS * N3];
__device__ unsigned char g_s3[(size_t)T_STEPS * N3];
__device__ float         g_c4[(size_t)T_STEPS * N4];

__device__ float g_skip1[80  * P1];
__device__ float g_skip2[160 * P2];
__device__ float g_skip3[320 * P3];
__device__ float g_skip4[640 * P4];

__device__ float g_d4[64 * P4];
__device__ float g_u4[64 * P3];
__device__ float g_d3[32 * P3];
__device__ float g_u3[32 * P2];
__device__ float g_d2[16 * P2];
__device__ float g_u2[16 * P1];
__device__ float g_d1[8  * P1];
__device__ float g_u1[8  * P0];

// Device-side buffer selectors (compile-time)
template<int L> __device__ __forceinline__ float* cbuf_of() {
    if constexpr (L == 2) return g_c2;
    else if constexpr (L == 3) return g_c3;
    else return g_c4;
}
template<int L> __device__ __forceinline__ unsigned char* sbuf_of() {
    if constexpr (L == 1) return g_s1;
    else if constexpr (L == 2) return g_s2;
    else return g_s3;
}
template<int L> __device__ __forceinline__ float* skip_of() {
    if constexpr (L == 2) return g_skip2;
    else if constexpr (L == 3) return g_skip3;
    else return g_skip4;
}

// ---------------------------------------------------------------------------
// FUSED layer 1 (tile-parallel): conv(stride2, SAME) + membrane scan.
// Block = 32 output cols x 4 oc of ONE output row chunk. Grid (6, 50).
// The 3x65 x-window for each timestep is staged through a depth-8 cp.async
// smem ring; one __syncthreads per step. Pipeline order per iteration:
//   wait_group(D-2) -> syncthreads -> compute(t) -> issue(t+D-1) -> commit
// Numerics identical to the split version: same fmaf tap order; zero-filled
// padding taps add exact +0; membrane scan arithmetic unchanged.
// ---------------------------------------------------------------------------
#define L1_D    8
#define L1_TILE 195   // 3 rows x 65 cols

__global__ void fused_l1_kernel(const float* __restrict__ x,
                                const float* __restrict__ w1,
                                const float* __restrict__ b1) {
    __shared__ float ring[L1_D][L1_TILE];

    const int chunk = blockIdx.x;          // 0..5  (32-wide col chunks)
    const int oh    = blockIdx.y;          // 0..49
    const int ow0   = chunk * 32;
    const int tid   = threadIdx.x;         // 128 threads
    const int oc    = tid & 3;
    const int j     = tid >> 2;            // 0..31 (local output col)
    const int ow    = ow0 + j;
    const bool act  = (ow < W1);
    const int pos   = oh * W1 + ow;

    float wv[9];
    #pragma unroll
    for (int i = 0; i < 9; i++) wv[i] = __ldg(&w1[oc * 9 + i]);
    const float bias = __ldg(&b1[oc]);

    const int gr0 = 2 * oh, gc0 = 2 * ow0;

    // issue cp.async loads for one timestep tile into a ring slot
    auto issue = [&](int slot, int t) {
        const float* xt = x + (size_t)t * P0;
        for (int i = tid; i < L1_TILE; i += 128) {
            int r = i / 65, cc = i - r * 65;
            int gr = gr0 + r, gc = gc0 + cc;
            bool v = (gr < H0) && (gc < W0);
            const float* src = v ? (xt + gr * W0 + gc) : x;
            unsigned int d = (unsigned int)__cvta_generic_to_shared(&ring[slot][i]);
            int sz = v ? 4 : 0;
            asm volatile("cp.async.ca.shared.global [%0], [%1], 4, %2;"
                         :: "r"(d), "l"(src), "r"(sz));
        }
        asm volatile("cp.async.commit_group;" ::: "memory");
    };

    // Prologue: tiles 0..D-2
    for (int d = 0; d < L1_D - 1; d++) issue(d, d);

    float m = 0.0f;
    int t = 0;
    for (int k = 0; k < KBINS; k++) {
        float sum = 0.0f, sq = 0.0f;
        for (int s = 0; s < SBIN; s++, t++) {
            asm volatile("cp.async.wait_group %0;" :: "n"(L1_D - 2) : "memory");
            __syncthreads();

            const float* xs = ring[t % L1_D];
            float cur = bias;
            #pragma unroll
            for (int kh = 0; kh < 3; kh++)
                #pragma unroll
                for (int kw = 0; kw < 3; kw++)
                    cur = __fmaf_rn(xs[kh * 65 + 2 * j + kw],
                                    wv[kh * 3 + kw], cur);

            // exact mul-then-add mirrors BETA*m + conv
            m = __fadd_rn(__fmul_rn(0.9f, m), cur);
            float u = __fadd_rn(m, -1.0f);
            bool spk = (u > 0.0f);
            if (act)
                g_s1[(size_t)t * N1 + pos * 4 + oc] =
                    spk ? (unsigned char)1 : (unsigned char)0;
            m = spk ? u : m;                 // soft reset (exact)
            sum = __fadd_rn(sum, m);
            sq  = __fmaf_rn(m, m, sq);

            // issue tile t+D-1 into slot (t-1)%D (safe: its readers finished
            // before the barrier above)
            int tt = t + L1_D - 1;
            if (tt < T_STEPS) issue(tt % L1_D, tt);
            else asm volatile("cp.async.commit_group;" ::: "memory");
        }
        if (act) {
            float mu  = __fdiv_rn(sum, (float)SBIN);
            float var = __fsub_rn(__fdiv_rn(sq, (float)SBIN), __fmul_rn(mu, mu));
            float sd  = __fsqrt_rn(fmaxf(var, 1e-8f));
            g_skip1[(size_t)(k * 8 + oc) * P1 + pos]     = mu;
            g_skip1[(size_t)(k * 8 + 4 + oc) * P1 + pos] = sd;
        }
    }
}

// ---------------------------------------------------------------------------
// Spike conv (stride 2, SAME), channel-last in AND out:
// one vector spike load per tap; COUT accumulators stored as float4 vectors.
// ---------------------------------------------------------------------------
template<int CIN, int COUT>
__device__ __forceinline__ void tap_accum_word(unsigned int v, const float* ws,
                                               int ic_base, int tap,
                                               float (&acc)[COUT]) {
    #pragma unroll
    for (int j = 0; j < 4 && ic_base + j < CIN; j++) {
        if ((v >> (8 * j)) & 0xffu) {
            const float* wv = &ws[((ic_base + j) * 9 + tap) * COUT];
            #pragma unroll
            for (int o = 0; o < COUT; o++)
                acc[o] = __fadd_rn(acc[o], wv[o]);
        }
    }
}

template<int L, int CIN, int COUT, int IH, int IW, int OH, int OW, int PH>
__global__ void convs_kernel(const float* __restrict__ w,
                             const float* __restrict__ b) {
    constexpr int P  = OH * OW;
    constexpr int NI = CIN * IH * IW;
    constexpr int NW = CIN * 9 * COUT;
    const unsigned char* __restrict__ spk = sbuf_of<L - 1>();
    float* __restrict__ cbuf = cbuf_of<L>();

    __shared__ __align__(16) float ws[NW];
    __shared__ float bs[COUT];
    for (int i = threadIdx.x; i < NW; i += blockDim.x) {
        int oc = i / (CIN * 9);
        int j  = i - oc * (CIN * 9);        // ic*9 + tap
        ws[j * COUT + oc] = w[i];
    }
    for (int i = threadIdx.x; i < COUT; i += blockDim.x) bs[i] = b[i];
    __syncthreads();

    int idx = blockIdx.x * blockDim.x + threadIdx.x;
    if (idx >= T_STEPS * P) return;
    int t = idx / P;
    int pos = idx - t * P;
    int oh = pos / OW, ow = pos - oh * OW;

    float acc[COUT];
    #pragma unroll
    for (int o = 0; o < COUT; o++) acc[o] = bs[o];

    const unsigned char* sp = spk + (size_t)t * NI;
    #pragma unroll
    for (int kh = 0; kh < 3; kh++) {
        int r = 2 * oh + kh - PH;
        if (r < 0 || r >= IH) continue;
        #pragma unroll
        for (int kw = 0; kw < 3; kw++) {
            int cc = 2 * ow + kw;
            if (cc >= IW) continue;
            int tap = kh * 3 + kw;
            const unsigned char* p = sp + (size_t)(r * IW + cc) * CIN;
            if constexpr (CIN == 4) {
                unsigned int v = __ldg((const unsigned int*)p);
                tap_accum_word<CIN, COUT>(v, ws, 0, tap, acc);
            } else if constexpr (CIN == 8) {
                uint2 v = __ldg((const uint2*)p);
                tap_accum_word<CIN, COUT>(v.x, ws, 0, tap, acc);
                tap_accum_word<CIN, COUT>(v.y, ws, 4, tap, acc);
            } else {  // CIN == 16
                uint4 v = __ldg((const uint4*)p);
                tap_accum_word<CIN, COUT>(v.x, ws, 0,  tap, acc);
                tap_accum_word<CIN, COUT>(v.y, ws, 4,  tap, acc);
                tap_accum_word<CIN, COUT>(v.z, ws, 8,  tap, acc);
                tap_accum_word<CIN, COUT>(v.w, ws, 12, tap, acc);
            }
        }
    }
    float4* out = (float4*)(cbuf + ((size_t)t * P + pos) * COUT);
    #pragma unroll
    for (int o = 0; o < COUT / 4; o++)
        out[o] = make_float4(acc[4 * o], acc[4 * o + 1],
                             acc[4 * o + 2], acc[4 * o + 3]);
}

// ---------------------------------------------------------------------------
// Per-neuron membrane scan (layers 2-4), channel-last thread mapping
// n' = pos*C + c; UF=50 A/B register prefetch (compile-time selection).
// ---------------------------------------------------------------------------
#define UF 50

template<int N, bool WRITE_S>
__device__ __forceinline__ void scan_group(const float* __restrict__ cp,
                                           unsigned char* __restrict__ sb,
                                           int tproc,
                                           float (&proc)[UF], float (&pre)[UF],
                                           float& m, float& sum, float& sq) {
    const int tpre = tproc + UF;
    if (tpre < T_STEPS) {
        #pragma unroll
        for (int j = 0; j < UF; j++)
            pre[j] = __ldg(cp + (size_t)(tpre + j) * N);
    }
    #pragma unroll
    for (int j = 0; j < UF; j++) {
        m = __fadd_rn(__fmul_rn(0.9f, m), proc[j]);
        float u = __fadd_rn(m, -1.0f);
        bool spk = (u > 0.0f);
        if (WRITE_S)
            sb[(size_t)(tproc + j) * N] = spk ? (unsigned char)1
                                              : (unsigned char)0;
        m = spk ? u : m;                    // soft reset (exact)
        sum = __fadd_rn(sum, m);
        sq  = __fmaf_rn(m, m, sq);
    }
}

template<int L, int C, int P, bool WRITE_S>
__global__ void scan_kernel() {
    constexpr int N = C * P;
    const float* __restrict__ cbuf = cbuf_of<L>();
    float* __restrict__ skip = skip_of<L>();

    int n = blockIdx.x * blockDim.x + threadIdx.x;   // n = pos*C + c
    if (n >= N) return;
    int pos = n / C, c = n - pos * C;

    const float* cp = cbuf + n;
    unsigned char* sb = (unsigned char*)0;
    if (WRITE_S) sb = sbuf_of<L>() + n;

    float A[UF], B[UF];
    #pragma unroll
    for (int j = 0; j < UF; j++) A[j] = __ldg(cp + (size_t)j * N);

    float m = 0.0f;
    int t = 0;
    for (int k = 0; k < KBINS; k++) {
        float sum = 0.0f, sq = 0.0f;
        scan_group<N, WRITE_S>(cp, sb, t, A, B, m, sum, sq); t += UF;
        scan_group<N, WRITE_S>(cp, sb, t, B, A, m, sum, sq); t += UF;

        float mu  = __fdiv_rn(sum, (float)SBIN);
        float var = __fsub_rn(__fdiv_rn(sq, (float)SBIN), __fmul_rn(mu, mu));
        float sd  = __fsqrt_rn(fmaxf(var, 1e-8f));
        skip[(size_t)(k * 2 * C + c) * P + pos]     = mu;
        skip[(size_t)(k * 2 * C + C + c) * P + pos] = sd;
    }
}

// ---------------------------------------------------------------------------
// Decoder stage 4 (640 -> 64 @ 7x23), ci-split 8 ways for occupancy.
// Block 256 = 32 pos x 8 ci-groups; weights for this oc staged in smem;
// fixed-order smem reduction keeps determinism.
// ---------------------------------------------------------------------------
__global__ void dconv4_split_kernel(const float* __restrict__ w,
                                    const float* __restrict__ b) {
    __shared__ float ws[640 * 9];       // 23 KB
    __shared__ float red[8][32];
    const int oc = blockIdx.y;
    const int tid = threadIdx.x;
    for (int i = tid; i < 640 * 9; i += 256) ws[i] = __ldg(&w[oc * 640 * 9 + i]);
    __syncthreads();

    const int j = tid & 31, q = tid >> 5;
    const int pos = blockIdx.x * 32 + j;
    const bool act = (pos < P4);
    const int pc = act ? pos : (P4 - 1);
    const int oh = pc / W4, ow = pc - oh * W4;

    bool rv[3], cv[3];
    #pragma unroll
    for (int kh = 0; kh < 3; kh++) { int r = oh + kh - 1; rv[kh] = (r >= 0 && r < H4); }
    #pragma unroll
    for (int kw = 0; kw < 3; kw++) { int cc = ow + kw - 1; cv[kw] = (cc >= 0 && cc < W4); }

    float a = 0.0f;
    const int ci0 = q * 80;
    for (int ci = ci0; ci < ci0 + 80; ci++) {
        const float* src = g_skip4 + (size_t)ci * P4;
        const float* wv = ws + ci * 9;
        #pragma unroll
        for (int kh = 0; kh < 3; kh++) {
            if (!rv[kh]) continue;
            int r = oh + kh - 1;
            #pragma unroll
            for (int kw = 0; kw < 3; kw++) {
                if (!cv[kw]) continue;
                int cc = ow + kw - 1;
                a = __fmaf_rn(__ldg(&src[r * W4 + cc]), wv[kh * 3 + kw], a);
            }
        }
    }
    red[q][j] = a;
    __syncthreads();
    if (q == 0 && act) {
        float tot = __ldg(&b[oc]);
        #pragma unroll
        for (int qq = 0; qq < 8; qq++) tot = __fadd_rn(tot, red[qq][j]);
        tot = fmaxf(tot, 0.0f);
        g_d4[(size_t)oc * P4 + pos] = tot;
    }
}

// ---------------------------------------------------------------------------
// Decoder conv (stages 3,2,1): stride 1, SAME, input = concat(in1, in2).
// ---------------------------------------------------------------------------
template<int STAGE, int C1, int C2, int COUT, int HH, int WW>
__global__ void dconv_kernel(const float* __restrict__ w,
                             const float* __restrict__ b) {
    constexpr int P = HH * WW;
    constexpr int CTOT = C1 + C2;
    const float* in1;
    const float* in2;
    float* outp;
    if constexpr (STAGE == 3) { in1 = g_u4; in2 = g_skip3; outp = g_d3; }
    else if constexpr (STAGE == 2) { in1 = g_u3; in2 = g_skip2; outp = g_d2; }
    else { in1 = g_u2; in2 = g_skip1; outp = g_d1; }

    int oc = blockIdx.y;
    int pos = blockIdx.x * blockDim.x + threadIdx.x;
    if (pos >= P) return;
    int oh = pos / WW, ow = pos - oh * WW;

    bool rv[3], cv[3];
    #pragma unroll
    for (int kh = 0; kh < 3; kh++) { int r = oh + kh - 1; rv[kh] = (r >= 0 && r < HH); }
    #pragma unroll
    for (int kw = 0; kw < 3; kw++) { int cc = ow + kw - 1; cv[kw] = (cc >= 0 && cc < WW); }

    const float* wrow = w + (size_t)oc * CTOT * 9;
    float acc[4] = {__ldg(&b[oc]), 0.0f, 0.0f, 0.0f};
    #pragma unroll 4
    for (int ci = 0; ci < CTOT; ci++) {
        const float* src = (ci < C1) ? (in1 + (size_t)ci * P)
                                     : (in2 + (size_t)(ci - C1) * P);
        const float* wv = wrow + ci * 9;
        float a = acc[ci & 3];
        #pragma unroll
        for (int kh = 0; kh < 3; kh++) {
            if (!rv[kh]) continue;
            int r = oh + kh - 1;
            #pragma unroll
            for (int kw = 0; kw < 3; kw++) {
                if (!cv[kw]) continue;
                int cc = ow + kw - 1;
                a = __fmaf_rn(__ldg(&src[r * WW + cc]), __ldg(&wv[kh * 3 + kw]), a);
            }
        }
        acc[ci & 3] = a;
    }
    float rres = __fadd_rn(__fadd_rn(acc[0], acc[1]), __fadd_rn(acc[2], acc[3]));
    rres = fmaxf(rres, 0.0f);
    outp[(size_t)oc * P + pos] = rres;
}

// ---------------------------------------------------------------------------
// Bilinear upsample (half-pixel centers, edge clamp).
// ---------------------------------------------------------------------------
template<int STAGE, int C, int IHH, int IWW, int OHH, int OWW>
__global__ void upsample_kernel() {
    constexpr int OP = OHH * OWW;
    constexpr int IP = IHH * IWW;
    const float* in;
    float* outp;
    if constexpr (STAGE == 4) { in = g_d4; outp = g_u4; }
    else if constexpr (STAGE == 3) { in = g_d3; outp = g_u3; }
    else if constexpr (STAGE == 2) { in = g_d2; outp = g_u2; }
    else { in = g_d1; outp = g_u1; }

    int idx = blockIdx.x * blockDim.x + threadIdx.x;
    if (idx >= C * OP) return;
    int cch = idx / OP;
    int rem = idx - cch * OP;
    int oh = rem / OWW, ow = rem - oh * OWW;

    float sy = (oh + 0.5f) * ((float)IHH / (float)OHH) - 0.5f;
    float sx = (ow + 0.5f) * ((float)IWW / (float)OWW) - 0.5f;
    float fy = floorf(sy), fx = floorf(sx);
    float wy = sy - fy, wx = sx - fx;
    int y0 = (int)fy, x0 = (int)fx;
    int y0c = max(y0, 0), y1c = min(y0 + 1, IHH - 1);
    int x0c = max(x0, 0), x1c = min(x0 + 1, IWW - 1);

    const float* src = in + (size_t)cch * IP;
    float v00 = __ldg(&src[y0c * IWW + x0c]);
    float v01 = __ldg(&src[y0c * IWW + x1c]);
    float v10 = __ldg(&src[y1c * IWW + x0c]);
    float v11 = __ldg(&src[y1c * IWW + x1c]);
    float top = __fadd_rn(__fmul_rn(1.0f - wx, v00), __fmul_rn(wx, v01));
    float bot = __fadd_rn(__fmul_rn(1.0f - wx, v10), __fmul_rn(wx, v11));
    outp[idx] = __fadd_rn(__fmul_rn(1.0f - wy, top), __fmul_rn(wy, bot));
}

// ---------------------------------------------------------------------------
// Final 1x1 conv: g_u1[8,100,368] -> out[1,100,368]
// ---------------------------------------------------------------------------
__global__ void outconv_kernel(const float* __restrict__ wo,
                               const float* __restrict__ bo,
                               float* __restrict__ out) {
    int pos = blockIdx.x * blockDim.x + threadIdx.x;
    if (pos >= P0) return;
    float acc = __ldg(&bo[0]);
    #pragma unroll
    for (int cch = 0; cch < 8; cch++)
        acc = __fmaf_rn(g_u1[cch * P0 + pos], __ldg(&wo[cch]), acc);
    out[pos] = acc;
}

// ---------------------------------------------------------------------------
// Host launcher: kernel launches ONLY.
// ---------------------------------------------------------------------------
static inline int cdiv(int a, int b) { return (a + b - 1) / b; }

extern "C" void kernel_launch(void* const* d_in, const int* in_sizes, int n_in,
                              void* d_out, int out_size) {
    const float* x   = (const float*)d_in[0];
    const float* w1  = (const float*)d_in[1];
    const float* b1  = (const float*)d_in[2];
    const float* w2  = (const float*)d_in[3];
    const float* b2  = (const float*)d_in[4];
    const float* w3  = (const float*)d_in[5];
    const float* b3  = (const float*)d_in[6];
    const float* w4  = (const float*)d_in[7];
    const float* b4  = (const float*)d_in[8];
    const float* dw4 = (const float*)d_in[9];
    const float* db4 = (const float*)d_in[10];
    const float* dw3 = (const float*)d_in[11];
    const float* db3 = (const float*)d_in[12];
    const float* dw2 = (const float*)d_in[13];
    const float* db2 = (const float*)d_in[14];
    const float* dw1 = (const float*)d_in[15];
    const float* db1 = (const float*)d_in[16];
    const float* wo  = (const float*)d_in[17];
    const float* bo  = (const float*)d_in[18];
    float* out = (float*)d_out;

    // ---- Encoder ----
    {   dim3 grid(6, 50);   // fused conv1 + scan1
        fused_l1_kernel<<<grid, 128>>>(x, w1, b1);
    }

    convs_kernel<2, 4, 8, H1, W1, H2, W2, 0>
        <<<cdiv(T_STEPS * P2, 128), 128>>>(w2, b2);
    scan_kernel<2, 8, P2, true><<<cdiv(N2, 128), 128>>>();

    convs_kernel<3, 8, 16, H2, W2, H3, W3, 1>
        <<<cdiv(T_STEPS * P3, 128), 128>>>(w3, b3);
    scan_kernel<3, 16, P3, true><<<cdiv(N3, 128), 128>>>();

    convs_kernel<4, 16, 32, H3, W3, H4, W4, 1>
        <<<cdiv(T_STEPS * P4, 128), 128>>>(w4, b4);
    scan_kernel<4, 32, P4, false><<<cdiv(N4, 128), 128>>>();

    // ---- Decoder ----
    {   dim3 grid(cdiv(P4, 32), 64);    // dec4: 640 -> 64 @ 7x23 (ci-split)
        dconv4_split_kernel<<<grid, 256>>>(dw4, db4);
    }
    upsample_kernel<4, 64, H4, W4, H3, W3><<<cdiv(64 * P3, 256), 256>>>();
    {   dim3 grid(cdiv(P3, 128), 32);   // dec3: 64+320 -> 32 @ 13x46
        dconv_kernel<3, 64, 320, 32, H3, W3><<<grid, 128>>>(dw3, db3);
    }
    upsample_kernel<3, 32, H3, W3, H2, W2><<<cdiv(32 * P2, 256), 256>>>();
    {   dim3 grid(cdiv(P2, 128), 16);   // dec2: 32+160 -> 16 @ 25x92
        dconv_kernel<2, 32, 160, 16, H2, W2><<<grid, 128>>>(dw2, db2);
    }
    upsample_kernel<2, 16, H2, W2, H1, W1><<<cdiv(16 * P1, 256), 256>>>();
    {   dim3 grid(cdiv(P1, 128), 8);    // dec1: 16+80 -> 8 @ 50x184
        dconv_kernel<1, 16, 80, 8, H1, W1><<<grid, 128>>>(dw1, db1);
    }
    upsample_kernel<1, 8, H1, W1, H0, W0><<<cdiv(8 * P0, 256), 256>>>();
    outconv_kernel<<<cdiv(P0, 256), 256>>>(wo, bo, out);
}

// round 15
// speedup vs baseline: 2.4040x; 1.8449x over previous
#include <cuda_runtime.h>
#include <cuda_bf16.h>
#include <cstdint>
#include <cstddef>

// ---------------------------------------------------------------------------
// Constants (total_steps=1000 -> K=10 bins of S=100)
// ---------------------------------------------------------------------------
#define T_STEPS 1000
#define SBIN    100
#define KBINS   10

#define H0 100
#define W0 368
#define H1 50
#define W1 184
#define H2 25
#define W2 92
#define H3 13
#define W3 46
#define H4 7
#define W4 23

#define P0 (H0*W0)   // 36800
#define P1 (H1*W1)   // 9200
#define P2 (H2*W2)   // 2300
#define P3 (H3*W3)   // 598
#define P4 (H4*W4)   // 161

#define N1 (4*P1)    // 36800
#define N2 (8*P2)    // 18400
#define N3 (16*P3)   // 9568
#define N4 (32*P4)   // 5152

// ---------------------------------------------------------------------------
// Scratch (device globals). Time-indexed data is CHANNEL-LAST:
//   currents c[t][pos][oc], spikes s[t][pos][ic].
// Layer 1 currents are never materialized (fused conv+scan).
// ---------------------------------------------------------------------------
__device__ unsigned char g_s1[(size_t)T_STEPS * N1];
__device__ float         g_c2[(size_t)T_STEPS * N2];
__device__ unsigned char g_s2[(size_t)T_STEPS * N2];
__device__ float         g_c3[(size_t)T_STEPS * N3];
__device__ unsigned char g_s3[(size_t)T_STEPS * N3];
__device__ float         g_c4[(size_t)T_STEPS * N4];

__device__ float g_skip1[80  * P1];
__device__ float g_skip2[160 * P2];
__device__ float g_skip3[320 * P3];
__device__ float g_skip4[640 * P4];

__device__ float g_d4[64 * P4];
__device__ float g_u4[64 * P3];
__device__ float g_d3[32 * P3];
__device__ float g_u3[32 * P2];
__device__ float g_d2[16 * P2];
__device__ float g_u2[16 * P1];
__device__ float g_d1[8  * P1];
__device__ float g_u1[8  * P0];

// Device-side buffer selectors (compile-time)
template<int L> __device__ __forceinline__ float* cbuf_of() {
    if constexpr (L == 2) return g_c2;
    else if constexpr (L == 3) return g_c3;
    else return g_c4;
}
template<int L> __device__ __forceinline__ unsigned char* sbuf_of() {
    if constexpr (L == 1) return g_s1;
    else if constexpr (L == 2) return g_s2;
    else return g_s3;
}
template<int L> __device__ __forceinline__ float* skip_of() {
    if constexpr (L == 2) return g_skip2;
    else if constexpr (L == 3) return g_skip3;
    else return g_skip4;
}

// ---------------------------------------------------------------------------
// FUSED layer 1 (tile-parallel): conv(stride2, SAME) + membrane scan.
// Block = 32 output cols x 4 oc of ONE output row chunk. Grid (6, 50).
// Depth-8 cp.async smem ring; per-thread load coordinates are hoisted OUT of
// the time loop (they were recomputed 2000x/thread before, incl. div by 65).
// ---------------------------------------------------------------------------
#define L1_D    8
#define L1_TILE 195   // 3 rows x 65 cols

__global__ void fused_l1_kernel(const float* __restrict__ x,
                                const float* __restrict__ w1,
                                const float* __restrict__ b1) {
    __shared__ float ring[L1_D][L1_TILE];

    const int chunk = blockIdx.x;          // 0..5  (32-wide col chunks)
    const int oh    = blockIdx.y;          // 0..49
    const int ow0   = chunk * 32;
    const int tid   = threadIdx.x;         // 128 threads
    const int oc    = tid & 3;
    const int j     = tid >> 2;            // 0..31 (local output col)
    const int ow    = ow0 + j;
    const bool act  = (ow < W1);
    const int pos   = oh * W1 + ow;

    float wv[9];
    #pragma unroll
    for (int i = 0; i < 9; i++) wv[i] = __ldg(&w1[oc * 9 + i]);
    const float bias = __ldg(&b1[oc]);

    const int gr0 = 2 * oh, gc0 = 2 * ow0;

    // Hoisted per-thread load descriptors (each thread fills <=2 tile slots)
    const unsigned ring_base =
        (unsigned)__cvta_generic_to_shared(&ring[0][0]);
    const int i0 = tid;
    const int r_0 = i0 / 65, cc_0 = i0 - r_0 * 65;
    const bool v_0 = (gr0 + r_0 < H0) && (gc0 + cc_0 < W0);
    const int go_0 = v_0 ? (gr0 + r_0) * W0 + (gc0 + cc_0) : 0;
    const int sz_0 = v_0 ? 4 : 0;
    const int i1 = tid + 128;
    const bool has1 = (i1 < L1_TILE);
    const int r_1 = i1 / 65, cc_1 = i1 - r_1 * 65;
    const bool v_1 = has1 && (gr0 + r_1 < H0) && (gc0 + cc_1 < W0);
    const int go_1 = v_1 ? (gr0 + r_1) * W0 + (gc0 + cc_1) : 0;
    const int sz_1 = v_1 ? 4 : 0;

    auto issue = [&](int slot, int t) {
        const float* xt = x + (size_t)t * P0;
        unsigned d0 = ring_base + (unsigned)(slot * L1_TILE + i0) * 4u;
        asm volatile("cp.async.ca.shared.global [%0], [%1], 4, %2;"
                     :: "r"(d0), "l"(xt + go_0), "r"(sz_0));
        if (has1) {
            unsigned d1 = ring_base + (unsigned)(slot * L1_TILE + i1) * 4u;
            asm volatile("cp.async.ca.shared.global [%0], [%1], 4, %2;"
                         :: "r"(d1), "l"(xt + go_1), "r"(sz_1));
        }
        asm volatile("cp.async.commit_group;" ::: "memory");
    };

    // Prologue: tiles 0..D-2
    for (int d = 0; d < L1_D - 1; d++) issue(d, d);

    float m = 0.0f;
    int t = 0;
    for (int k = 0; k < KBINS; k++) {
        float sum = 0.0f, sq = 0.0f;
        for (int s = 0; s < SBIN; s++, t++) {
            asm volatile("cp.async.wait_group %0;" :: "n"(L1_D - 2) : "memory");
            __syncthreads();

            const float* xs = ring[t % L1_D];
            float cur = bias;
            #pragma unroll
            for (int kh = 0; kh < 3; kh++)
                #pragma unroll
                for (int kw = 0; kw < 3; kw++)
                    cur = __fmaf_rn(xs[kh * 65 + 2 * j + kw],
                                    wv[kh * 3 + kw], cur);

            // exact mul-then-add mirrors BETA*m + conv
            m = __fadd_rn(__fmul_rn(0.9f, m), cur);
            float u = __fadd_rn(m, -1.0f);
            bool spk = (u > 0.0f);
            if (act)
                g_s1[(size_t)t * N1 + pos * 4 + oc] =
                    spk ? (unsigned char)1 : (unsigned char)0;
            m = spk ? u : m;                 // soft reset (exact)
            sum = __fadd_rn(sum, m);
            sq  = __fmaf_rn(m, m, sq);

            int tt = t + L1_D - 1;
            if (tt < T_STEPS) issue(tt % L1_D, tt);
            else asm volatile("cp.async.commit_group;" ::: "memory");
        }
        if (act) {
            float mu  = __fdiv_rn(sum, (float)SBIN);
            float var = __fsub_rn(__fdiv_rn(sq, (float)SBIN), __fmul_rn(mu, mu));
            float sd  = __fsqrt_rn(fmaxf(var, 1e-8f));
            g_skip1[(size_t)(k * 8 + oc) * P1 + pos]     = mu;
            g_skip1[(size_t)(k * 8 + 4 + oc) * P1 + pos] = sd;
        }
    }
}

// ---------------------------------------------------------------------------
// Spike conv (stride 2, SAME), channel-last in AND out.
// ALL 9 tap words are preloaded into registers (independent LDGs; invalid
// taps load exact 0-words) BEFORE any accumulation -> the per-tap L1 latency
// is overlapped instead of serialized behind the branchy adds.
// Accumulation order (tap-major, ic ascending, oc ascending) is unchanged.
// ---------------------------------------------------------------------------
template<int CIN, int COUT>
__device__ __forceinline__ void tap_accum_word(unsigned int v, const float* ws,
                                               int ic_base, int tap,
                                               float (&acc)[COUT]) {
    #pragma unroll
    for (int j = 0; j < 4 && ic_base + j < CIN; j++) {
        if ((v >> (8 * j)) & 0xffu) {
            const float* wv = &ws[((ic_base + j) * 9 + tap) * COUT];
            #pragma unroll
            for (int o = 0; o < COUT; o++)
                acc[o] = __fadd_rn(acc[o], wv[o]);
        }
    }
}

template<int L, int CIN, int COUT, int IH, int IW, int OH, int OW, int PH>
__global__ void convs_kernel(const float* __restrict__ w,
                             const float* __restrict__ b) {
    constexpr int P  = OH * OW;
    constexpr int NI = CIN * IH * IW;
    constexpr int NW = CIN * 9 * COUT;
    const unsigned char* __restrict__ spk = sbuf_of<L - 1>();
    float* __restrict__ cbuf = cbuf_of<L>();

    __shared__ __align__(16) float ws[NW];
    __shared__ float bs[COUT];
    for (int i = threadIdx.x; i < NW; i += blockDim.x) {
        int oc = i / (CIN * 9);
        int j  = i - oc * (CIN * 9);        // ic*9 + tap
        ws[j * COUT + oc] = w[i];
    }
    for (int i = threadIdx.x; i < COUT; i += blockDim.x) bs[i] = b[i];
    __syncthreads();

    int idx = blockIdx.x * blockDim.x + threadIdx.x;
    if (idx >= T_STEPS * P) return;
    int t = idx / P;
    int pos = idx - t * P;
    int oh = pos / OW, ow = pos - oh * OW;

    float acc[COUT];
    #pragma unroll
    for (int o = 0; o < COUT; o++) acc[o] = bs[o];

    const unsigned char* sp = spk + (size_t)t * NI;

    if constexpr (CIN == 4) {
        unsigned int v[9];
        #pragma unroll
        for (int kh = 0; kh < 3; kh++)
            #pragma unroll
            for (int kw = 0; kw < 3; kw++) {
                int tap = kh * 3 + kw;
                int r = 2 * oh + kh - PH, cc = 2 * ow + kw;
                bool val = (r >= 0) && (r < IH) && (cc < IW);
                v[tap] = val
                    ? __ldg((const unsigned int*)(sp + (size_t)(r * IW + cc) * CIN))
                    : 0u;
            }
        #pragma unroll
        for (int tap = 0; tap < 9; tap++)
            tap_accum_word<CIN, COUT>(v[tap], ws, 0, tap, acc);
    } else if constexpr (CIN == 8) {
        uint2 v[9];
        #pragma unroll
        for (int kh = 0; kh < 3; kh++)
            #pragma unroll
            for (int kw = 0; kw < 3; kw++) {
                int tap = kh * 3 + kw;
                int r = 2 * oh + kh - PH, cc = 2 * ow + kw;
                bool val = (r >= 0) && (r < IH) && (cc < IW);
                v[tap] = val
                    ? __ldg((const uint2*)(sp + (size_t)(r * IW + cc) * CIN))
                    : make_uint2(0u, 0u);
            }
        #pragma unroll
        for (int tap = 0; tap < 9; tap++) {
            tap_accum_word<CIN, COUT>(v[tap].x, ws, 0, tap, acc);
            tap_accum_word<CIN, COUT>(v[tap].y, ws, 4, tap, acc);
        }
    } else {  // CIN == 16
        uint4 v[9];
        #pragma unroll
        for (int kh = 0; kh < 3; kh++)
            #pragma unroll
            for (int kw = 0; kw < 3; kw++) {
                int tap = kh * 3 + kw;
                int r = 2 * oh + kh - PH, cc = 2 * ow + kw;
                bool val = (r >= 0) && (r < IH) && (cc < IW);
                v[tap] = val
                    ? __ldg((const uint4*)(sp + (size_t)(r * IW + cc) * CIN))
                    : make_uint4(0u, 0u, 0u, 0u);
            }
        #pragma unroll
        for (int tap = 0; tap < 9; tap++) {
            tap_accum_word<CIN, COUT>(v[tap].x, ws, 0,  tap, acc);
            tap_accum_word<CIN, COUT>(v[tap].y, ws, 4,  tap, acc);
            tap_accum_word<CIN, COUT>(v[tap].z, ws, 8,  tap, acc);
            tap_accum_word<CIN, COUT>(v[tap].w, ws, 12, tap, acc);
        }
    }

    float4* out = (float4*)(cbuf + ((size_t)t * P + pos) * COUT);
    #pragma unroll
    for (int o = 0; o < COUT / 4; o++)
        out[o] = make_float4(acc[4 * o], acc[4 * o + 1],
                             acc[4 * o + 2], acc[4 * o + 3]);
}

// ---------------------------------------------------------------------------
// Per-neuron membrane scan (layers 2-4), channel-last thread mapping
// n' = pos*C + c; UF=50 A/B register prefetch (compile-time selection).
// ---------------------------------------------------------------------------
#define UF 50

template<int N, bool WRITE_S>
__device__ __forceinline__ void scan_group(const float* __restrict__ cp,
                                           unsigned char* __restrict__ sb,
                                           int tproc,
                                           float (&proc)[UF], float (&pre)[UF],
                                           float& m, float& sum, float& sq) {
    const int tpre = tproc + UF;
    if (tpre < T_STEPS) {
        #pragma unroll
        for (int j = 0; j < UF; j++)
            pre[j] = __ldg(cp + (size_t)(tpre + j) * N);
    }
    #pragma unroll
    for (int j = 0; j < UF; j++) {
        m = __fadd_rn(__fmul_rn(0.9f, m), proc[j]);
        float u = __fadd_rn(m, -1.0f);
        bool spk = (u > 0.0f);
        if (WRITE_S)
            sb[(size_t)(tproc + j) * N] = spk ? (unsigned char)1
                                              : (unsigned char)0;
        m = spk ? u : m;                    // soft reset (exact)
        sum = __fadd_rn(sum, m);
        sq  = __fmaf_rn(m, m, sq);
    }
}

template<int L, int C, int P, bool WRITE_S>
__global__ void scan_kernel() {
    constexpr int N = C * P;
    const float* __restrict__ cbuf = cbuf_of<L>();
    float* __restrict__ skip = skip_of<L>();

    int n = blockIdx.x * blockDim.x + threadIdx.x;   // n = pos*C + c
    if (n >= N) return;
    int pos = n / C, c = n - pos * C;

    const float* cp = cbuf + n;
    unsigned char* sb = (unsigned char*)0;
    if (WRITE_S) sb = sbuf_of<L>() + n;

    float A[UF], B[UF];
    #pragma unroll
    for (int j = 0; j < UF; j++) A[j] = __ldg(cp + (size_t)j * N);

    float m = 0.0f;
    int t = 0;
    for (int k = 0; k < KBINS; k++) {
        float sum = 0.0f, sq = 0.0f;
        scan_group<N, WRITE_S>(cp, sb, t, A, B, m, sum, sq); t += UF;
        scan_group<N, WRITE_S>(cp, sb, t, B, A, m, sum, sq); t += UF;

        float mu  = __fdiv_rn(sum, (float)SBIN);
        float var = __fsub_rn(__fdiv_rn(sq, (float)SBIN), __fmul_rn(mu, mu));
        float sd  = __fsqrt_rn(fmaxf(var, 1e-8f));
        skip[(size_t)(k * 2 * C + c) * P + pos]     = mu;
        skip[(size_t)(k * 2 * C + C + c) * P + pos] = sd;
    }
}

// ---------------------------------------------------------------------------
// Decoder stage 4 (640 -> 64 @ 7x23), ci-split 8 ways (unchanged from R13).
// ---------------------------------------------------------------------------
__global__ void dconv4_split_kernel(const float* __restrict__ w,
                                    const float* __restrict__ b) {
    __shared__ float ws[640 * 9];       // 23 KB
    __shared__ float red[8][32];
    const int oc = blockIdx.y;
    const int tid = threadIdx.x;
    for (int i = tid; i < 640 * 9; i += 256) ws[i] = __ldg(&w[oc * 640 * 9 + i]);
    __syncthreads();

    const int j = tid & 31, q = tid >> 5;
    const int pos = blockIdx.x * 32 + j;
    const bool act = (pos < P4);
    const int pc = act ? pos : (P4 - 1);
    const int oh = pc / W4, ow = pc - oh * W4;

    bool rv[3], cv[3];
    #pragma unroll
    for (int kh = 0; kh < 3; kh++) { int r = oh + kh - 1; rv[kh] = (r >= 0 && r < H4); }
    #pragma unroll
    for (int kw = 0; kw < 3; kw++) { int cc = ow + kw - 1; cv[kw] = (cc >= 0 && cc < W4); }

    float a = 0.0f;
    const int ci0 = q * 80;
    for (int ci = ci0; ci < ci0 + 80; ci++) {
        const float* src = g_skip4 + (size_t)ci * P4;
        const float* wv = ws + ci * 9;
        #pragma unroll
        for (int kh = 0; kh < 3; kh++) {
            if (!rv[kh]) continue;
            int r = oh + kh - 1;
            #pragma unroll
            for (int kw = 0; kw < 3; kw++) {
                if (!cv[kw]) continue;
                int cc = ow + kw - 1;
                a = __fmaf_rn(__ldg(&src[r * W4 + cc]), wv[kh * 3 + kw], a);
            }
        }
    }
    red[q][j] = a;
    __syncthreads();
    if (q == 0 && act) {
        float tot = __ldg(&b[oc]);
        #pragma unroll
        for (int qq = 0; qq < 8; qq++) tot = __fadd_rn(tot, red[qq][j]);
        tot = fmaxf(tot, 0.0f);
        g_d4[(size_t)oc * P4 + pos] = tot;
    }
}

// ---------------------------------------------------------------------------
// Decoder stages 3/2/1: ci-split 4 ways, weights staged in smem (halves LDG
// count and breaks the weight-load dependency), 3 rotating accumulators
// (by kh) shorten the FMA chain. Block = 32 pos x 4 ci-groups = 128 threads.
// ---------------------------------------------------------------------------
template<int STAGE, int C1, int C2, int COUT, int HH, int WW>
__global__ void dconv_split_kernel(const float* __restrict__ w,
                                   const float* __restrict__ b) {
    constexpr int P = HH * WW;
    constexpr int CTOT = C1 + C2;
    constexpr int CPG = CTOT / 4;
    const float* in1;
    const float* in2;
    float* outp;
    if constexpr (STAGE == 3) { in1 = g_u4; in2 = g_skip3; outp = g_d3; }
    else if constexpr (STAGE == 2) { in1 = g_u3; in2 = g_skip2; outp = g_d2; }
    else { in1 = g_u2; in2 = g_skip1; outp = g_d1; }

    __shared__ float ws[CTOT * 9];
    __shared__ float red[4][32];
    const int oc = blockIdx.y;
    const int tid = threadIdx.x;
    for (int i = tid; i < CTOT * 9; i += 128) ws[i] = __ldg(&w[oc * CTOT * 9 + i]);
    __syncthreads();

    const int j = tid & 31, q = tid >> 5;
    const int pos = blockIdx.x * 32 + j;
    const bool act = (pos < P);
    const int pc = act ? pos : (P - 1);
    const int oh = pc / WW, ow = pc - oh * WW;

    bool rv[3], cv[3];
    #pragma unroll
    for (int kh = 0; kh < 3; kh++) { int r = oh + kh - 1; rv[kh] = (r >= 0 && r < HH); }
    #pragma unroll
    for (int kw = 0; kw < 3; kw++) { int cc = ow + kw - 1; cv[kw] = (cc >= 0 && cc < WW); }

    float a0 = 0.0f, a1 = 0.0f, a2 = 0.0f;
    const int ci0 = q * CPG;
    #pragma unroll 2
    for (int ci = ci0; ci < ci0 + CPG; ci++) {
        const float* src = (ci < C1) ? (in1 + (size_t)ci * P)
                                     : (in2 + (size_t)(ci - C1) * P);
        const float* wv = ws + ci * 9;
        #pragma unroll
        for (int kh = 0; kh < 3; kh++) {
            if (!rv[kh]) continue;
            int r = oh + kh - 1;
            float aa = (kh == 0) ? a0 : (kh == 1) ? a1 : a2;
            #pragma unroll
            for (int kw = 0; kw < 3; kw++) {
                if (!cv[kw]) continue;
                int cc = ow + kw - 1;
                aa = __fmaf_rn(__ldg(&src[r * WW + cc]), wv[kh * 3 + kw], aa);
            }
            if (kh == 0) a0 = aa; else if (kh == 1) a1 = aa; else a2 = aa;
        }
    }
    red[q][j] = __fadd_rn(__fadd_rn(a0, a1), a2);
    __syncthreads();
    if (q == 0 && act) {
        float tot = __ldg(&b[oc]);
        #pragma unroll
        for (int qq = 0; qq < 4; qq++) tot = __fadd_rn(tot, red[qq][j]);
        tot = fmaxf(tot, 0.0f);
        outp[(size_t)oc * P + pos] = tot;
    }
}

// ---------------------------------------------------------------------------
// Bilinear upsample (half-pixel centers, edge clamp).
// ---------------------------------------------------------------------------
template<int STAGE, int C, int IHH, int IWW, int OHH, int OWW>
__global__ void upsample_kernel() {
    constexpr int OP = OHH * OWW;
    constexpr int IP = IHH * IWW;
    const float* in;
    float* outp;
    if constexpr (STAGE == 4) { in = g_d4; outp = g_u4; }
    else if constexpr (STAGE == 3) { in = g_d3; outp = g_u3; }
    else if constexpr (STAGE == 2) { in = g_d2; outp = g_u2; }
    else { in = g_d1; outp = g_u1; }

    int idx = blockIdx.x * blockDim.x + threadIdx.x;
    if (idx >= C * OP) return;
    int cch = idx / OP;
    int rem = idx - cch * OP;
    int oh = rem / OWW, ow = rem - oh * OWW;

    float sy = (oh + 0.5f) * ((float)IHH / (float)OHH) - 0.5f;
    float sx = (ow + 0.5f) * ((float)IWW / (float)OWW) - 0.5f;
    float fy = floorf(sy), fx = floorf(sx);
    float wy = sy - fy, wx = sx - fx;
    int y0 = (int)fy, x0 = (int)fx;
    int y0c = max(y0, 0), y1c = min(y0 + 1, IHH - 1);
    int x0c = max(x0, 0), x1c = min(x0 + 1, IWW - 1);

    const float* src = in + (size_t)cch * IP;
    float v00 = __ldg(&src[y0c * IWW + x0c]);
    float v01 = __ldg(&src[y0c * IWW + x1c]);
    float v10 = __ldg(&src[y1c * IWW + x0c]);
    float v11 = __ldg(&src[y1c * IWW + x1c]);
    float top = __fadd_rn(__fmul_rn(1.0f - wx, v00), __fmul_rn(wx, v01));
    float bot = __fadd_rn(__fmul_rn(1.0f - wx, v10), __fmul_rn(wx, v11));
    outp[idx] = __fadd_rn(__fmul_rn(1.0f - wy, top), __fmul_rn(wy, bot));
}

// ---------------------------------------------------------------------------
// Final 1x1 conv: g_u1[8,100,368] -> out[1,100,368]
// ---------------------------------------------------------------------------
__global__ void outconv_kernel(const float* __restrict__ wo,
                               const float* __restrict__ bo,
                               float* __restrict__ out) {
    int pos = blockIdx.x * blockDim.x + threadIdx.x;
    if (pos >= P0) return;
    float acc = __ldg(&bo[0]);
    #pragma unroll
    for (int cch = 0; cch < 8; cch++)
        acc = __fmaf_rn(g_u1[cch * P0 + pos], __ldg(&wo[cch]), acc);
    out[pos] = acc;
}

// ---------------------------------------------------------------------------
// Host launcher: kernel launches ONLY.
// ---------------------------------------------------------------------------
static inline int cdiv(int a, int b) { return (a + b - 1) / b; }

extern "C" void kernel_launch(void* const* d_in, const int* in_sizes, int n_in,
                              void* d_out, int out_size) {
    const float* x   = (const float*)d_in[0];
    const float* w1  = (const float*)d_in[1];
    const float* b1  = (const float*)d_in[2];
    const float* w2  = (const float*)d_in[3];
    const float* b2  = (const float*)d_in[4];
    const float* w3  = (const float*)d_in[5];
    const float* b3  = (const float*)d_in[6];
    const float* w4  = (const float*)d_in[7];
    const float* b4  = (const float*)d_in[8];
    const float* dw4 = (const float*)d_in[9];
    const float* db4 = (const float*)d_in[10];
    const float* dw3 = (const float*)d_in[11];
    const float* db3 = (const float*)d_in[12];
    const float* dw2 = (const float*)d_in[13];
    const float* db2 = (const float*)d_in[14];
    const float* dw1 = (const float*)d_in[15];
    const float* db1 = (const float*)d_in[16];
    const float* wo  = (const float*)d_in[17];
    const float* bo  = (const float*)d_in[18];
    float* out = (float*)d_out;

    // ---- Encoder ----
    {   dim3 grid(6, 50);   // fused conv1 + scan1
        fused_l1_kernel<<<grid, 128>>>(x, w1, b1);
    }

    convs_kernel<2, 4, 8, H1, W1, H2, W2, 0>
        <<<cdiv(T_STEPS * P2, 128), 128>>>(w2, b2);
    scan_kernel<2, 8, P2, true><<<cdiv(N2, 128), 128>>>();

    convs_kernel<3, 8, 16, H2, W2, H3, W3, 1>
        <<<cdiv(T_STEPS * P3, 128), 128>>>(w3, b3);
    scan_kernel<3, 16, P3, true><<<cdiv(N3, 128), 128>>>();

    convs_kernel<4, 16, 32, H3, W3, H4, W4, 1>
        <<<cdiv(T_STEPS * P4, 128), 128>>>(w4, b4);
    scan_kernel<4, 32, P4, false><<<cdiv(N4, 128), 128>>>();

    // ---- Decoder ----
    {   dim3 grid(cdiv(P4, 32), 64);    // dec4: 640 -> 64 @ 7x23 (ci-split x8)
        dconv4_split_kernel<<<grid, 256>>>(dw4, db4);
    }
    upsample_kernel<4, 64, H4, W4, H3, W3><<<cdiv(64 * P3, 256), 256>>>();
    {   dim3 grid(cdiv(P3, 32), 32);    // dec3: 384 -> 32 @ 13x46 (ci-split x4)
        dconv_split_kernel<3, 64, 320, 32, H3, W3><<<grid, 128>>>(dw3, db3);
    }
    upsample_kernel<3, 32, H3, W3, H2, W2><<<cdiv(32 * P2, 256), 256>>>();
    {   dim3 grid(cdiv(P2, 32), 16);    // dec2: 192 -> 16 @ 25x92 (ci-split x4)
        dconv_split_kernel<2, 32, 160, 16, H2, W2><<<grid, 128>>>(dw2, db2);
    }
    upsample_kernel<2, 16, H2, W2, H1, W1><<<cdiv(16 * P1, 256), 256>>>();
    {   dim3 grid(cdiv(P1, 32), 8);     // dec1: 96 -> 8 @ 50x184 (ci-split x4)
        dconv_split_kernel<1, 16, 80, 8, H1, W1><<<grid, 128>>>(dw1, db1);
    }
    upsample_kernel<1, 8, H1, W1, H0, W0><<<cdiv(8 * P0, 256), 256>>>();
    outconv_kernel<<<cdiv(P0, 256), 256>>>(wo, bo, out);
}